// round 1
// baseline (speedup 1.0000x reference)
#include <cuda_runtime.h>
#include <cstdint>

#define A_NUM 9
#define KA_MAX 36864   // 64*64*9
#define N_MAX  36864
#define B_MAX  32
#define G_MAX  64

struct Params { int B, G, H, W, KA, N; };
__device__ Params g_p;
__device__ int    g_rank[KA_MAX];          // inside rank or -1
__device__ float4 g_anc4[N_MAX];           // inside anchor boxes
__device__ uint32_t g_keyf[B_MAX * 2];     // per-image fg subsample key
__device__ uint32_t g_keyb[B_MAX * 2];     // per-image bg subsample key
__device__ float  g_gtmax[B_MAX * G_MAX];
__device__ int    g_arg[B_MAX * N_MAX];
__device__ signed char g_lab[B_MAX * N_MAX];
__device__ uint32_t g_pf[B_MAX * N_MAX];   // fg priority bits (23-bit)
__device__ uint32_t g_pb[B_MAX * N_MAX];   // bg priority bits

// ---------------- Threefry-2x32 (20 rounds), exactly JAX's schedule ----------
__device__ __forceinline__ uint32_t rotl32(uint32_t x, uint32_t r) {
    return (x << r) | (x >> (32u - r));
}
__device__ __forceinline__ void tf2x32(uint32_t k0, uint32_t k1,
                                       uint32_t& x0, uint32_t& x1) {
    uint32_t ks2 = k0 ^ k1 ^ 0x1BD11BDAu;
    x0 += k0; x1 += k1;
    const uint32_t rA[4] = {13u, 15u, 26u, 6u};
    const uint32_t rB[4] = {17u, 29u, 16u, 24u};
#pragma unroll
    for (int i = 0; i < 4; i++) { x0 += x1; x1 = rotl32(x1, rA[i]); x1 ^= x0; }
    x0 += k1; x1 += ks2 + 1u;
#pragma unroll
    for (int i = 0; i < 4; i++) { x0 += x1; x1 = rotl32(x1, rB[i]); x1 ^= x0; }
    x0 += ks2; x1 += k0 + 2u;
#pragma unroll
    for (int i = 0; i < 4; i++) { x0 += x1; x1 = rotl32(x1, rA[i]); x1 ^= x0; }
    x0 += k0; x1 += k1 + 3u;
#pragma unroll
    for (int i = 0; i < 4; i++) { x0 += x1; x1 = rotl32(x1, rB[i]); x1 ^= x0; }
    x0 += k1; x1 += ks2 + 4u;
#pragma unroll
    for (int i = 0; i < 4; i++) { x0 += x1; x1 = rotl32(x1, rA[i]); x1 ^= x0; }
    x0 += ks2; x1 += k0 + 5u;
}

// ---------------- IoU, identical op order everywhere (no FMA contraction) ----
__device__ __forceinline__ float iou_fn(float a0, float a1, float a2, float a3,
                                        float areaa,
                                        float g0, float g1, float g2, float g3,
                                        float areag) {
    float iw = __fadd_rn(__fsub_rn(fminf(a2, g2), fmaxf(a0, g0)), 1.0f);
    float ih = __fadd_rn(__fsub_rn(fminf(a3, g3), fmaxf(a1, g1)), 1.0f);
    iw = fmaxf(iw, 0.0f);
    ih = fmaxf(ih, 0.0f);
    float inter = __fmul_rn(iw, ih);
    float denom = __fsub_rn(__fadd_rn(areaa, areag), inter);
    return __fdiv_rn(inter, denom);
}
__device__ __forceinline__ float area_fn(float x1, float y1, float x2, float y2) {
    return __fmul_rn(__fadd_rn(__fsub_rn(x2, x1), 1.0f),
                     __fadd_rn(__fsub_rn(y2, y1), 1.0f));
}

// ---------------- K1: params + anchors + inside compaction (1 block) ---------
__global__ void k_setup(const int* pB, const int* pG, const int* pH, const int* pW) {
    const int tid = threadIdx.x;
    const int bd = 1024;
    __shared__ float sanch[A_NUM * 4];
    __shared__ int s_scan[1024];
    __shared__ int s_carry;
    if (tid == 0) {
        int B = *pB, G = *pG, H = *pH, W = *pW;
        if (B > B_MAX) B = B_MAX;
        if (G > G_MAX) G = G_MAX;
        g_p.B = B; g_p.G = G; g_p.H = H; g_p.W = W;
        int KA = H * W * A_NUM;
        if (KA > KA_MAX) KA = KA_MAX;
        g_p.KA = KA;
        // base anchors: 3 ratios x 3 scales, numpy round-half-even via rint
        const double ratios[3] = {0.5, 1.0, 2.0};
        const double scales[3] = {8.0, 16.0, 32.0};
        for (int r = 0; r < 3; r++) {
            double ws = rint(sqrt(256.0 / ratios[r]));
            double hs = rint(ws * ratios[r]);
            for (int s = 0; s < 3; s++) {
                double Wd = ws * scales[s], Hd = hs * scales[s];
                int idx = (r * 3 + s) * 4;
                sanch[idx + 0] = (float)(7.5 - 0.5 * (Wd - 1.0));
                sanch[idx + 1] = (float)(7.5 - 0.5 * (Hd - 1.0));
                sanch[idx + 2] = (float)(7.5 + 0.5 * (Wd - 1.0));
                sanch[idx + 3] = (float)(7.5 + 0.5 * (Hd - 1.0));
            }
        }
        s_carry = 0;
    }
    __syncthreads();
    const int KA = g_p.KA;
    const int W = g_p.W;
    const float img_w = 16.0f * (float)g_p.W;
    const float img_h = 16.0f * (float)g_p.H;
    for (int base = 0; base < KA; base += bd) {
        int ka = base + tid;
        float x1 = 0.f, y1 = 0.f, x2 = 0.f, y2 = 0.f;
        int f = 0;
        if (ka < KA) {
            int a = ka % A_NUM;
            int cell = ka / A_NUM;
            int cx = cell % W, cy = cell / W;
            float sx = 16.0f * (float)cx, sy = 16.0f * (float)cy;
            x1 = sx + sanch[a * 4 + 0];
            y1 = sy + sanch[a * 4 + 1];
            x2 = sx + sanch[a * 4 + 2];
            y2 = sy + sanch[a * 4 + 3];
            f = (x1 >= 0.f && y1 >= 0.f && x2 < img_w && y2 < img_h) ? 1 : 0;
        }
        // inclusive Hillis-Steele scan of f
        int v = f;
        for (int off = 1; off < bd; off <<= 1) {
            s_scan[tid] = v;
            __syncthreads();
            if (tid >= off) v += s_scan[tid - off];
            __syncthreads();
        }
        int excl = s_carry + v - f;
        if (ka < KA) {
            if (f) {
                g_rank[ka] = excl;
                g_anc4[excl] = make_float4(x1, y1, x2, y2);
            } else {
                g_rank[ka] = -1;
            }
        }
        __syncthreads();
        if (tid == bd - 1) s_carry += v;
        __syncthreads();
    }
    if (tid == 0) g_p.N = s_carry;
}

// ---------------- K2: per-image subsample keys (partitionable threefry) ------
// keys    = split(key(42)=(0,42), B):   keys[b]   = tf((0,42),(0,b))   (both words)
// kf,kb   = split(keys[b], 2):          kf = tf(keys_b,(0,0)), kb = tf(keys_b,(0,1))
__global__ void k_keys() {
    int b = blockIdx.x * blockDim.x + threadIdx.x;
    if (b >= g_p.B) return;
    uint32_t h0 = 0u, h1 = (uint32_t)b;
    tf2x32(0u, 42u, h0, h1);
    uint32_t f0 = 0u, f1 = 0u; tf2x32(h0, h1, f0, f1);
    uint32_t c0 = 0u, c1 = 1u; tf2x32(h0, h1, c0, c1);
    g_keyf[b * 2 + 0] = f0; g_keyf[b * 2 + 1] = f1;
    g_keyb[b * 2 + 0] = c0; g_keyb[b * 2 + 1] = c1;
}

// ---------------- K3: per-(b,g) max IoU over anchors -------------------------
__global__ void k_gtmax(const float* __restrict__ gt) {
    int g = blockIdx.x, b = blockIdx.y;
    if (b >= g_p.B || g >= g_p.G) return;
    const int N = g_p.N;
    const float* gp = gt + ((size_t)b * g_p.G + g) * 4;
    float g0 = gp[0], g1 = gp[1], g2 = gp[2], g3 = gp[3];
    float areag = area_fn(g0, g1, g2, g3);
    float m = 0.0f;
    for (int i = threadIdx.x; i < N; i += 256) {
        float4 a = g_anc4[i];
        float areaa = area_fn(a.x, a.y, a.z, a.w);
        m = fmaxf(m, iou_fn(a.x, a.y, a.z, a.w, areaa, g0, g1, g2, g3, areag));
    }
    __shared__ float sm[256];
    sm[threadIdx.x] = m;
    __syncthreads();
    for (int off = 128; off > 0; off >>= 1) {
        if (threadIdx.x < off) sm[threadIdx.x] = fmaxf(sm[threadIdx.x], sm[threadIdx.x + off]);
        __syncthreads();
    }
    if (threadIdx.x == 0) g_gtmax[b * G_MAX + g] = sm[0];
}

// ---------------- K4: per-(b,i) labels + argmax ------------------------------
__global__ void k_labels(const float* __restrict__ gt) {
    int b = blockIdx.y;
    if (b >= g_p.B) return;
    const int N = g_p.N, G = g_p.G;
    __shared__ float sgt[G_MAX * 4];
    __shared__ float sga[G_MAX];
    __shared__ float sgm[G_MAX];
    for (int j = threadIdx.x; j < G * 4; j += blockDim.x)
        sgt[j] = gt[(size_t)b * G * 4 + j];
    for (int j = threadIdx.x; j < G; j += blockDim.x)
        sgm[j] = g_gtmax[b * G_MAX + j];
    __syncthreads();
    for (int j = threadIdx.x; j < G; j += blockDim.x)
        sga[j] = area_fn(sgt[j * 4], sgt[j * 4 + 1], sgt[j * 4 + 2], sgt[j * 4 + 3]);
    __syncthreads();
    int i = blockIdx.x * blockDim.x + threadIdx.x;
    if (i >= N) return;
    float4 a = g_anc4[i];
    float areaa = area_fn(a.x, a.y, a.z, a.w);
    float best = 0.0f;
    int arg = 0;
    int hit = 0;
    for (int g = 0; g < G; g++) {
        float iou = iou_fn(a.x, a.y, a.z, a.w, areaa,
                           sgt[g * 4], sgt[g * 4 + 1], sgt[g * 4 + 2], sgt[g * 4 + 3],
                           sga[g]);
        if (iou > best) { best = iou; arg = g; }
        if (iou == sgm[g] && sgm[g] > 0.0f) hit = 1;
    }
    signed char lab = -1;
    if (best < 0.3f) lab = 0;
    if (best >= 0.7f) lab = 1;
    if (hit) lab = 1;
    g_lab[(size_t)b * N_MAX + i] = lab;
    g_arg[(size_t)b * N_MAX + i] = arg;
}

// ---------------- K5: priorities (uniform bits >> 9, partitionable) ----------
// bits[i] = o0 ^ o1 of tf(key, (0, i)); priority order == float order
__global__ void k_prio() {
    int b = blockIdx.y;
    if (b >= g_p.B) return;
    const int N = g_p.N;
    int i = blockIdx.x * blockDim.x + threadIdx.x;
    if (i >= N) return;
    uint32_t kf0 = g_keyf[b * 2], kf1 = g_keyf[b * 2 + 1];
    uint32_t kb0 = g_keyb[b * 2], kb1 = g_keyb[b * 2 + 1];
    uint32_t a0 = 0u, a1 = (uint32_t)i;
    tf2x32(kf0, kf1, a0, a1);
    g_pf[(size_t)b * N_MAX + i] = (a0 ^ a1) >> 9;
    uint32_t c0 = 0u, c1 = (uint32_t)i;
    tf2x32(kb0, kb1, c0, c1);
    g_pb[(size_t)b * N_MAX + i] = (c0 ^ c1) >> 9;
}

// ---------------- K6: exact radix-select + label rewrite (1 block/image) -----
__device__ unsigned long long radix_select_block(const uint32_t* __restrict__ prio,
                                                 const signed char* __restrict__ lab,
                                                 signed char want, int N, int k) {
    __shared__ int hist[256];
    __shared__ unsigned long long s_pref;
    __shared__ int s_k;
    unsigned long long prefix = 0ull;
    int kk = k;
    for (int shift = 32; shift >= 0; shift -= 8) {
        for (int j = threadIdx.x; j < 256; j += blockDim.x) hist[j] = 0;
        __syncthreads();
        for (int i = threadIdx.x; i < N; i += blockDim.x) {
            if (lab[i] == want) {
                unsigned long long key =
                    ((unsigned long long)prio[i] << 16) | (unsigned)i;
                if ((key >> (shift + 8)) == (prefix >> (shift + 8)))
                    atomicAdd(&hist[(int)((key >> shift) & 255ull)], 1);
            }
        }
        __syncthreads();
        if (threadIdx.x == 0) {
            int cum = 0, d = 0;
            for (; d < 256; d++) {
                int c = hist[d];
                if (cum + c >= kk) break;
                cum += c;
            }
            s_pref = prefix | ((unsigned long long)d << shift);
            s_k = kk - cum;
        }
        __syncthreads();
        prefix = s_pref;
        kk = s_k;
        __syncthreads();
    }
    return prefix;  // exact k-th smallest key (keys are unique)
}

__global__ void k_select() {
    int b = blockIdx.x;
    if (b >= g_p.B) return;
    const int N = g_p.N;
    signed char* lab = g_lab + (size_t)b * N_MAX;
    const uint32_t* pf = g_pf + (size_t)b * N_MAX;
    const uint32_t* pb = g_pb + (size_t)b * N_MAX;
    __shared__ int s_fg, s_bg;
    if (threadIdx.x == 0) { s_fg = 0; s_bg = 0; }
    __syncthreads();
    int fg = 0, bg = 0;
    for (int i = threadIdx.x; i < N; i += blockDim.x) {
        signed char l = lab[i];
        fg += (l == 1);
        bg += (l == 0);
    }
    atomicAdd(&s_fg, fg);
    atomicAdd(&s_bg, bg);
    __syncthreads();
    int fgcnt = s_fg, bgcnt = s_bg;
    unsigned long long fthr = ~0ull, bthr = ~0ull;
    if (fgcnt > 128) fthr = radix_select_block(pf, lab, 1, N, 128);
    int numbg = 256 - (fgcnt < 128 ? fgcnt : 128);
    if (bgcnt > numbg) bthr = radix_select_block(pb, lab, 0, N, numbg);
    __syncthreads();
    for (int i = threadIdx.x; i < N; i += blockDim.x) {
        signed char l = lab[i];
        if (l == 1) {
            unsigned long long key = ((unsigned long long)pf[i] << 16) | (unsigned)i;
            if (key > fthr) lab[i] = -1;
        } else if (l == 0) {
            unsigned long long key = ((unsigned long long)pb[i] << 16) | (unsigned)i;
            if (key > bthr) lab[i] = -1;
        }
    }
}

// ---------------- K7: emit labels [B,9,H,W] + reg [B,36,H,W] -----------------
__global__ void k_emit(const float* __restrict__ gt, float* __restrict__ out) {
    int b = blockIdx.y;
    if (b >= g_p.B) return;
    const int H = g_p.H, W = g_p.W, HW = H * W, KA = g_p.KA, G = g_p.G, B = g_p.B;
    int t = blockIdx.x * blockDim.x + threadIdx.x;  // linear over (a, y, x)
    if (t >= KA) return;
    int a = t / HW;
    int rem = t - a * HW;                  // y*W + x
    int ka = rem * A_NUM + a;
    int rank = g_rank[ka];
    float lv = -1.0f;
    float r0 = 0.f, r1 = 0.f, r2 = 0.f, r3 = 0.f;
    if (rank >= 0) {
        signed char l = g_lab[(size_t)b * N_MAX + rank];
        lv = (float)l;
        if (l == 1) {
            int arg = g_arg[(size_t)b * N_MAX + rank];
            float4 av = g_anc4[rank];
            const float* gp = gt + ((size_t)b * G + arg) * 4;
            float g0 = gp[0], g1 = gp[1], g2 = gp[2], g3 = gp[3];
            float aw = av.z - av.x + 1.0f, ah = av.w - av.y + 1.0f;
            float acx = av.x + 0.5f * (aw - 1.0f), acy = av.y + 0.5f * (ah - 1.0f);
            float gw = g2 - g0 + 1.0f, gh = g3 - g1 + 1.0f;
            float gcx = g0 + 0.5f * (gw - 1.0f), gcy = g1 + 0.5f * (gh - 1.0f);
            r0 = (gcx - acx) / aw;
            r1 = (gcy - acy) / ah;
            r2 = logf(gw / aw);
            r3 = logf(gh / ah);
        }
    }
    // labels: [B, A, H, W]
    out[((size_t)b * A_NUM + a) * HW + rem] = lv;
    // reg: [B, A*4, H, W], channel = a*4 + d
    float* out_reg = out + (size_t)B * A_NUM * HW;
    size_t rb = ((size_t)b * A_NUM * 4 + (size_t)a * 4) * HW + rem;
    out_reg[rb] = r0;
    out_reg[rb + HW] = r1;
    out_reg[rb + 2 * (size_t)HW] = r2;
    out_reg[rb + 3 * (size_t)HW] = r3;
}

extern "C" void kernel_launch(void* const* d_in, const int* in_sizes, int n_in,
                              void* d_out, int out_size) {
    const float* gt = (const float*)d_in[0];
    const int* pB = (const int*)d_in[1];
    const int* pG = (const int*)d_in[2];
    const int* pH = (const int*)d_in[3];
    const int* pW = (const int*)d_in[4];

    k_setup<<<1, 1024>>>(pB, pG, pH, pW);
    k_keys<<<1, 64>>>();
    {
        dim3 g(G_MAX, B_MAX);
        k_gtmax<<<g, 256>>>(gt);
    }
    {
        dim3 g((N_MAX + 255) / 256, B_MAX);
        k_labels<<<g, 256>>>(gt);
    }
    {
        dim3 g((N_MAX + 255) / 256, B_MAX);
        k_prio<<<g, 256>>>();
    }
    k_select<<<B_MAX, 1024>>>();
    {
        dim3 g((KA_MAX + 255) / 256, B_MAX);
        k_emit<<<g, 256>>>(gt, (float*)d_out);
    }
}

// round 2
// speedup vs baseline: 1.4506x; 1.4506x over previous
#include <cuda_runtime.h>
#include <cstdint>
#include <math_constants.h>

#define A_NUM 9
#define KA_MAX 36864   // 64*64*9
#define N_MAX  36864
#define B_MAX  32
#define G_MAX  64

struct Params { int B, G, H, W, KA, N; };
__device__ Params g_p;
__device__ int    g_rank[KA_MAX];            // inside rank or -1
__device__ float4 g_anc4[N_MAX];             // inside anchor boxes
__device__ float4 g_abox[A_NUM];             // base anchor offsets (float)
__device__ int4   g_bnd[A_NUM];              // {Lx,Rx,Ly,Ry} valid ranges
__device__ uint32_t g_keyf[B_MAX * 2];
__device__ uint32_t g_keyb[B_MAX * 2];
__device__ int    g_gtmax[B_MAX * G_MAX];    // float bits, atomicMax as int (iou>=0)
__device__ float  g_maxov[B_MAX * N_MAX];
__device__ unsigned char g_arg[B_MAX * N_MAX];
__device__ signed char g_lab[B_MAX * N_MAX];
__device__ uint32_t g_prio[B_MAX * N_MAX];   // 23-bit priority (fg or bg, exclusive)

// ---------------- Threefry-2x32 (JAX schedule) -------------------------------
__device__ __forceinline__ uint32_t rotl32(uint32_t x, uint32_t r) {
    return (x << r) | (x >> (32u - r));
}
__device__ __forceinline__ void tf2x32(uint32_t k0, uint32_t k1,
                                       uint32_t& x0, uint32_t& x1) {
    uint32_t ks2 = k0 ^ k1 ^ 0x1BD11BDAu;
    x0 += k0; x1 += k1;
    const uint32_t rA[4] = {13u, 15u, 26u, 6u};
    const uint32_t rB[4] = {17u, 29u, 16u, 24u};
#pragma unroll
    for (int i = 0; i < 4; i++) { x0 += x1; x1 = rotl32(x1, rA[i]); x1 ^= x0; }
    x0 += k1; x1 += ks2 + 1u;
#pragma unroll
    for (int i = 0; i < 4; i++) { x0 += x1; x1 = rotl32(x1, rB[i]); x1 ^= x0; }
    x0 += ks2; x1 += k0 + 2u;
#pragma unroll
    for (int i = 0; i < 4; i++) { x0 += x1; x1 = rotl32(x1, rA[i]); x1 ^= x0; }
    x0 += k0; x1 += k1 + 3u;
#pragma unroll
    for (int i = 0; i < 4; i++) { x0 += x1; x1 = rotl32(x1, rB[i]); x1 ^= x0; }
    x0 += k1; x1 += ks2 + 4u;
#pragma unroll
    for (int i = 0; i < 4; i++) { x0 += x1; x1 = rotl32(x1, rA[i]); x1 ^= x0; }
    x0 += ks2; x1 += k0 + 5u;
}

// ---------------- IoU (identical op order everywhere; no FMA contraction) ----
__device__ __forceinline__ float iou_fn(float a0, float a1, float a2, float a3,
                                        float areaa,
                                        float g0, float g1, float g2, float g3,
                                        float areag) {
    float iw = __fadd_rn(__fsub_rn(fminf(a2, g2), fmaxf(a0, g0)), 1.0f);
    float ih = __fadd_rn(__fsub_rn(fminf(a3, g3), fmaxf(a1, g1)), 1.0f);
    iw = fmaxf(iw, 0.0f);
    ih = fmaxf(ih, 0.0f);
    float inter = __fmul_rn(iw, ih);
    float denom = __fsub_rn(__fadd_rn(areaa, areag), inter);
    return __fdiv_rn(inter, denom);
}
__device__ __forceinline__ float area_fn(float x1, float y1, float x2, float y2) {
    return __fmul_rn(__fadd_rn(__fsub_rn(x2, x1), 1.0f),
                     __fadd_rn(__fsub_rn(y2, y1), 1.0f));
}

// ---------------- K0: params + base anchors + bounds + keys (1 block) --------
__global__ void k_setup0(const int* pB, const int* pG, const int* pH, const int* pW) {
    int t = threadIdx.x;
    if (t == 0) {
        int B = *pB, G = *pG, H = *pH, W = *pW;
        if (B > B_MAX) B = B_MAX;
        if (G > G_MAX) G = G_MAX;
        g_p.B = B; g_p.G = G; g_p.H = H; g_p.W = W;
        int KA = H * W * A_NUM;
        if (KA > KA_MAX) KA = KA_MAX;
        g_p.KA = KA;
        const double ratios[3] = {0.5, 1.0, 2.0};
        const double scales[3] = {8.0, 16.0, 32.0};
        int Ntot = 0;
        for (int r = 0; r < 3; r++) {
            double ws = rint(sqrt(256.0 / ratios[r]));
            double hs = rint(ws * ratios[r]);
            for (int s = 0; s < 3; s++) {
                double Wd = ws * scales[s], Hd = hs * scales[s];
                int a = r * 3 + s;
                double x1 = 7.5 - 0.5 * (Wd - 1.0);
                double y1 = 7.5 - 0.5 * (Hd - 1.0);
                double x2 = 7.5 + 0.5 * (Wd - 1.0);
                double y2 = 7.5 + 0.5 * (Hd - 1.0);
                g_abox[a] = make_float4((float)x1, (float)y1, (float)x2, (float)y2);
                int ix1 = (int)llrint(x1), iy1 = (int)llrint(y1);
                int ix2 = (int)llrint(x2), iy2 = (int)llrint(y2);
                int Lx = (ix1 < 0) ? ((-ix1 + 15) / 16) : 0;
                int Ly = (iy1 < 0) ? ((-iy1 + 15) / 16) : 0;
                int nxw = 16 * W - 1 - ix2;
                int nyh = 16 * H - 1 - iy2;
                int Rx = (nxw < 0) ? -1 : min(W - 1, nxw / 16);
                int Ry = (nyh < 0) ? -1 : min(H - 1, nyh / 16);
                g_bnd[a] = make_int4(Lx, Rx, Ly, Ry);
                int nx = Rx - Lx + 1; if (nx < 0) nx = 0;
                int ny = Ry - Ly + 1; if (ny < 0) ny = 0;
                Ntot += nx * ny;
            }
        }
        g_p.N = Ntot;
    }
    if (t < B_MAX) {
        uint32_t h0 = 0u, h1 = (uint32_t)t;
        tf2x32(0u, 42u, h0, h1);
        uint32_t f0 = 0u, f1 = 0u; tf2x32(h0, h1, f0, f1);
        uint32_t c0 = 0u, c1 = 1u; tf2x32(h0, h1, c0, c1);
        g_keyf[t * 2 + 0] = f0; g_keyf[t * 2 + 1] = f1;
        g_keyb[t * 2 + 0] = c0; g_keyb[t * 2 + 1] = c1;
    }
}

// ---------------- K1: analytic rank + anchor compaction + gtmax reset --------
__global__ void k_grid() {
    __shared__ int4 sb[A_NUM];
    __shared__ float4 sbx[A_NUM];
    int tid = threadIdx.x;
    if (tid < A_NUM) { sb[tid] = g_bnd[tid]; sbx[tid] = g_abox[tid]; }
    __syncthreads();
    int ka = blockIdx.x * blockDim.x + tid;
    if (ka < B_MAX * G_MAX) g_gtmax[ka] = 0;
    const int KA = g_p.KA, W = g_p.W;
    if (ka >= KA) return;
    int a = ka % A_NUM;
    int cell = ka / A_NUM;
    int x = cell % W, y = cell / W;
    int rank = 0;
#pragma unroll
    for (int a2 = 0; a2 < A_NUM; a2++) {
        int4 bb = sb[a2];  // {Lx,Rx,Ly,Ry}
        int nx = bb.y - bb.x + 1; if (nx < 0) nx = 0;
        int rb = min(bb.w, y - 1) - bb.z + 1; if (rb < 0) rb = 0;
        rank += rb * nx;
        if (y >= bb.z && y <= bb.w) {
            int xb = min(bb.y, x - 1) - bb.x + 1; if (xb < 0) xb = 0;
            rank += xb;
            if (a2 < a && x >= bb.x && x <= bb.y) rank += 1;
        }
    }
    int4 mb = sb[a];
    bool inside = (x >= mb.x && x <= mb.y && y >= mb.z && y <= mb.w);
    if (inside) {
        float sx = 16.0f * (float)x, sy = 16.0f * (float)y;
        float4 o = sbx[a];
        g_rank[ka] = rank;
        g_anc4[rank] = make_float4(sx + o.x, sy + o.y, sx + o.z, sy + o.w);
    } else {
        g_rank[ka] = -1;
    }
}

// ---------------- K2: pass A — max_ov, argmax, per-gt max (fused) ------------
#define APT 4
__global__ void __launch_bounds__(256, 2) k_passA(const float* __restrict__ gt) {
    int b = blockIdx.y;
    if (b >= g_p.B) return;
    const int N = g_p.N, G = g_p.G;
    int base = blockIdx.x * (256 * APT);
    if (base >= N) return;
    __shared__ float4 sgt[G_MAX];
    __shared__ float sga[G_MAX];
    __shared__ int sgmx[G_MAX];
    int tid = threadIdx.x;
    if (tid < G_MAX) {
        float4 gb;
        if (tid < G) gb = reinterpret_cast<const float4*>(gt)[(size_t)b * G + tid];
        else gb = make_float4(2e9f, 2e9f, -2e9f, -2e9f);
        sgt[tid] = gb;
        sga[tid] = area_fn(gb.x, gb.y, gb.z, gb.w);
        sgmx[tid] = 0;
    }
    __syncthreads();
    float4 A[APT]; float area[APT]; float best[APT]; int arg[APT]; bool val[APT];
#pragma unroll
    for (int k = 0; k < APT; k++) {
        int idx = base + k * 256 + tid;
        val[k] = idx < N;
        A[k] = val[k] ? g_anc4[idx] : make_float4(3e9f, 3e9f, -3e9f, -3e9f);
        area[k] = area_fn(A[k].x, A[k].y, A[k].z, A[k].w);
        best[k] = 0.0f; arg[k] = 0;
    }
    float gmax[G_MAX];
#pragma unroll
    for (int g = 0; g < G_MAX; g++) gmax[g] = 0.0f;
#pragma unroll
    for (int g = 0; g < G_MAX; g++) {
        if (g < G) {
            float4 gb = sgt[g]; float ag = sga[g];
            float m = gmax[g];
#pragma unroll
            for (int k = 0; k < APT; k++) {
                float iou = iou_fn(A[k].x, A[k].y, A[k].z, A[k].w, area[k],
                                   gb.x, gb.y, gb.z, gb.w, ag);
                if (iou > best[k]) { best[k] = iou; arg[k] = g; }
                m = fmaxf(m, iou);
            }
            gmax[g] = m;
        }
    }
    // reduce per-gt max: warp shuffle then shared atomic
#pragma unroll
    for (int g = 0; g < G_MAX; g++) {
        float v = gmax[g];
#pragma unroll
        for (int off = 16; off > 0; off >>= 1)
            v = fmaxf(v, __shfl_xor_sync(0xFFFFFFFFu, v, off));
        if ((tid & 31) == 0 && v > 0.0f) atomicMax(&sgmx[g], __float_as_int(v));
    }
    __syncthreads();
    if (tid < G) {
        int m = sgmx[tid];
        if (m != 0) atomicMax(&g_gtmax[b * G_MAX + tid], m);
    }
#pragma unroll
    for (int k = 0; k < APT; k++) {
        if (val[k]) {
            int idx = base + k * 256 + tid;
            g_maxov[(size_t)b * N_MAX + idx] = best[k];
            g_arg[(size_t)b * N_MAX + idx] = (unsigned char)arg[k];
        }
    }
}

// ---------------- K3: pass B — labels (with pruned hit test) + priority ------
__global__ void k_passB(const float* __restrict__ gt) {
    int b = blockIdx.y;
    if (b >= g_p.B) return;
    const int N = g_p.N, G = g_p.G;
    __shared__ float4 sgt[G_MAX];
    __shared__ float sga[G_MAX];
    __shared__ float sgm[G_MAX];
    __shared__ float s_red[G_MAX];
    __shared__ float s_gmin;
    int tid = threadIdx.x;
    if (tid < G_MAX) {
        float4 gb = make_float4(0, 0, 0, 0);
        float gm = 0.0f;
        if (tid < G) {
            gb = reinterpret_cast<const float4*>(gt)[(size_t)b * G + tid];
            gm = __int_as_float(g_gtmax[b * G_MAX + tid]);
        }
        sgt[tid] = gb;
        sga[tid] = area_fn(gb.x, gb.y, gb.z, gb.w);
        sgm[tid] = gm;
        s_red[tid] = (tid < G && gm > 0.0f) ? gm : CUDART_INF_F;
    }
    __syncthreads();
    if (tid < 32) {
        float v = fminf(s_red[tid], s_red[tid + 32]);
#pragma unroll
        for (int off = 16; off > 0; off >>= 1)
            v = fminf(v, __shfl_xor_sync(0xFFFFFFFFu, v, off));
        if (tid == 0) s_gmin = v;
    }
    __syncthreads();
    int i = blockIdx.x * blockDim.x + tid;
    if (i >= N) return;
    float maxov = g_maxov[(size_t)b * N_MAX + i];
    signed char lab = -1;
    if (maxov < 0.3f) lab = 0;
    if (maxov >= 0.7f) lab = 1;
    if (maxov >= s_gmin) {  // only these can achieve a per-gt max
        float4 a = g_anc4[i];
        float areaa = area_fn(a.x, a.y, a.z, a.w);
        for (int g = 0; g < G; g++) {
            float gm = sgm[g];
            if (gm > 0.0f && gm <= maxov) {
                float4 gb = sgt[g];
                float iou = iou_fn(a.x, a.y, a.z, a.w, areaa,
                                   gb.x, gb.y, gb.z, gb.w, sga[g]);
                if (iou == gm) { lab = 1; break; }
            }
        }
    }
    g_lab[(size_t)b * N_MAX + i] = lab;
    if (lab >= 0) {
        const uint32_t* kp = (lab == 1) ? g_keyf : g_keyb;
        uint32_t c0 = 0u, c1 = (uint32_t)i;
        tf2x32(kp[b * 2], kp[b * 2 + 1], c0, c1);
        g_prio[(size_t)b * N_MAX + i] = (c0 ^ c1) >> 9;
    }
}

// ---------------- K4: 2-stage exact k-th-smallest + label rewrite ------------
#define SEL_BUF 1024
__device__ unsigned long long select_kth(const uint32_t* __restrict__ prio,
                                         const signed char* __restrict__ lab,
                                         signed char want, int N, int kk,
                                         int* hist, unsigned long long* buf,
                                         int* s_i, unsigned long long* s_thr) {
    int tid = threadIdx.x;
    for (int j = tid; j < 256; j += blockDim.x) hist[j] = 0;
    if (tid == 0) { s_i[0] = 0; }
    __syncthreads();
    for (int i = tid; i < N; i += blockDim.x)
        if (lab[i] == want) atomicAdd(&hist[prio[i] >> 15], 1);
    __syncthreads();
    if (tid == 0) {
        int cum = 0, d = 0;
        for (; d < 256; d++) {
            int c = hist[d];
            if (cum + c >= kk) break;
            cum += c;
        }
        s_i[1] = d;          // bin
        s_i[2] = kk - cum;   // local rank (1-indexed)
    }
    __syncthreads();
    int d = s_i[1], lk = s_i[2];
    for (int i = tid; i < N; i += blockDim.x) {
        if (lab[i] == want && (int)(prio[i] >> 15) == d) {
            int pos = atomicAdd(&s_i[0], 1);
            if (pos < SEL_BUF)
                buf[pos] = ((unsigned long long)prio[i] << 16) | (unsigned)i;
        }
    }
    __syncthreads();
    int m = min(s_i[0], SEL_BUF);
    if (tid < m) {
        unsigned long long key = buf[tid];
        int c = 0;
        for (int j = 0; j < m; j++) c += (buf[j] < key);
        if (c == lk - 1) *s_thr = key;
    }
    __syncthreads();
    unsigned long long r = *s_thr;
    __syncthreads();
    return r;
}

__global__ void k_select() {
    int b = blockIdx.x;
    if (b >= g_p.B) return;
    const int N = g_p.N;
    signed char* lab = g_lab + (size_t)b * N_MAX;
    const uint32_t* prio = g_prio + (size_t)b * N_MAX;
    __shared__ int hist[256];
    __shared__ unsigned long long buf[SEL_BUF];
    __shared__ int s_i[4];
    __shared__ unsigned long long s_thr;
    __shared__ int s_fg, s_bg;
    int tid = threadIdx.x;
    if (tid == 0) { s_fg = 0; s_bg = 0; }
    __syncthreads();
    int fg = 0, bg = 0;
    for (int i = tid; i < N; i += blockDim.x) {
        signed char l = lab[i];
        fg += (l == 1);
        bg += (l == 0);
    }
    atomicAdd(&s_fg, fg);
    atomicAdd(&s_bg, bg);
    __syncthreads();
    int fgcnt = s_fg, bgcnt = s_bg;
    unsigned long long fthr = ~0ull, bthr = ~0ull;
    if (fgcnt > 128) {
        if (tid == 0) s_thr = ~0ull;
        __syncthreads();
        fthr = select_kth(prio, lab, 1, N, 128, hist, buf, s_i, &s_thr);
    }
    int numbg = 256 - (fgcnt < 128 ? fgcnt : 128);
    if (bgcnt > numbg) {
        if (tid == 0) s_thr = ~0ull;
        __syncthreads();
        bthr = select_kth(prio, lab, 0, N, numbg, hist, buf, s_i, &s_thr);
    }
    __syncthreads();
    for (int i = tid; i < N; i += blockDim.x) {
        signed char l = lab[i];
        if (l == 1 || l == 0) {
            unsigned long long key = ((unsigned long long)prio[i] << 16) | (unsigned)i;
            unsigned long long thr = (l == 1) ? fthr : bthr;
            if (key > thr) lab[i] = -1;
        }
    }
}

// ---------------- K5: emit labels [B,9,H,W] + reg [B,36,H,W] -----------------
__global__ void k_emit(const float* __restrict__ gt, float* __restrict__ out) {
    int b = blockIdx.y;
    if (b >= g_p.B) return;
    const int H = g_p.H, W = g_p.W, HW = H * W, KA = g_p.KA, G = g_p.G, B = g_p.B;
    int t = blockIdx.x * blockDim.x + threadIdx.x;  // linear over (a, y, x)
    if (t >= KA) return;
    int a = t / HW;
    int rem = t - a * HW;
    int ka = rem * A_NUM + a;
    int rank = g_rank[ka];
    float lv = -1.0f;
    float r0 = 0.f, r1 = 0.f, r2 = 0.f, r3 = 0.f;
    if (rank >= 0) {
        signed char l = g_lab[(size_t)b * N_MAX + rank];
        lv = (float)l;
        if (l == 1) {
            int arg = g_arg[(size_t)b * N_MAX + rank];
            float4 av = g_anc4[rank];
            const float* gp = gt + ((size_t)b * G + arg) * 4;
            float g0 = gp[0], g1 = gp[1], g2 = gp[2], g3 = gp[3];
            float aw = av.z - av.x + 1.0f, ah = av.w - av.y + 1.0f;
            float acx = av.x + 0.5f * (aw - 1.0f), acy = av.y + 0.5f * (ah - 1.0f);
            float gw = g2 - g0 + 1.0f, gh = g3 - g1 + 1.0f;
            float gcx = g0 + 0.5f * (gw - 1.0f), gcy = g1 + 0.5f * (gh - 1.0f);
            r0 = (gcx - acx) / aw;
            r1 = (gcy - acy) / ah;
            r2 = logf(gw / aw);
            r3 = logf(gh / ah);
        }
    }
    out[((size_t)b * A_NUM + a) * HW + rem] = lv;
    float* out_reg = out + (size_t)B * A_NUM * HW;
    size_t rb = ((size_t)b * A_NUM * 4 + (size_t)a * 4) * HW + rem;
    out_reg[rb] = r0;
    out_reg[rb + HW] = r1;
    out_reg[rb + 2 * (size_t)HW] = r2;
    out_reg[rb + 3 * (size_t)HW] = r3;
}

extern "C" void kernel_launch(void* const* d_in, const int* in_sizes, int n_in,
                              void* d_out, int out_size) {
    const float* gt = (const float*)d_in[0];
    const int* pB = (const int*)d_in[1];
    const int* pG = (const int*)d_in[2];
    const int* pH = (const int*)d_in[3];
    const int* pW = (const int*)d_in[4];

    k_setup0<<<1, 64>>>(pB, pG, pH, pW);
    k_grid<<<(KA_MAX + 255) / 256, 256>>>();
    {
        dim3 g((N_MAX + 256 * APT - 1) / (256 * APT), B_MAX);
        k_passA<<<g, 256>>>(gt);
    }
    {
        dim3 g((N_MAX + 255) / 256, B_MAX);
        k_passB<<<g, 256>>>(gt);
    }
    k_select<<<B_MAX, 1024>>>();
    {
        dim3 g((KA_MAX + 255) / 256, B_MAX);
        k_emit<<<g, 256>>>(gt, (float*)d_out);
    }
}

// round 3
// speedup vs baseline: 1.9995x; 1.3784x over previous
#include <cuda_runtime.h>
#include <cstdint>
#include <math_constants.h>

#define A_NUM 9
#define KA_MAX 36864   // 64*64*9
#define N_MAX  36864
#define B_MAX  32
#define G_MAX  64

struct Params { int B, G, H, W, KA, N; };
__device__ Params g_p;
__device__ int    g_rank[KA_MAX];            // inside rank or -1
__device__ float4 g_anc4[N_MAX];             // inside anchor boxes
__device__ float4 g_abox[A_NUM];             // base anchor offsets
__device__ int4   g_bnd[A_NUM];              // {Lx,Rx,Ly,Ry} valid cell ranges
__device__ uint32_t g_keyf[B_MAX * 2];
__device__ uint32_t g_keyb[B_MAX * 2];
__device__ int    g_gtmax[B_MAX * G_MAX];    // float bits, atomicMax as int (iou>=0)
__device__ unsigned char g_arg[B_MAX * N_MAX];
__device__ signed char g_lab[B_MAX * N_MAX];
__device__ uint32_t g_prio[B_MAX * N_MAX];   // 23-bit priority (fg or bg, exclusive)

// ---------------- Threefry-2x32 (JAX schedule) -------------------------------
__device__ __forceinline__ uint32_t rotl32(uint32_t x, uint32_t r) {
    return __funnelshift_l(x, x, r);
}
__device__ __forceinline__ void tf2x32(uint32_t k0, uint32_t k1,
                                       uint32_t& x0, uint32_t& x1) {
    uint32_t ks2 = k0 ^ k1 ^ 0x1BD11BDAu;
    x0 += k0; x1 += k1;
    const uint32_t rA[4] = {13u, 15u, 26u, 6u};
    const uint32_t rB[4] = {17u, 29u, 16u, 24u};
#pragma unroll
    for (int i = 0; i < 4; i++) { x0 += x1; x1 = rotl32(x1, rA[i]); x1 ^= x0; }
    x0 += k1; x1 += ks2 + 1u;
#pragma unroll
    for (int i = 0; i < 4; i++) { x0 += x1; x1 = rotl32(x1, rB[i]); x1 ^= x0; }
    x0 += ks2; x1 += k0 + 2u;
#pragma unroll
    for (int i = 0; i < 4; i++) { x0 += x1; x1 = rotl32(x1, rA[i]); x1 ^= x0; }
    x0 += k0; x1 += k1 + 3u;
#pragma unroll
    for (int i = 0; i < 4; i++) { x0 += x1; x1 = rotl32(x1, rB[i]); x1 ^= x0; }
    x0 += k1; x1 += ks2 + 4u;
#pragma unroll
    for (int i = 0; i < 4; i++) { x0 += x1; x1 = rotl32(x1, rA[i]); x1 ^= x0; }
    x0 += ks2; x1 += k0 + 5u;
}

// ---------------- IoU (identical op order everywhere; no FMA contraction) ----
__device__ __forceinline__ float iou_fn(float a0, float a1, float a2, float a3,
                                        float areaa,
                                        float g0, float g1, float g2, float g3,
                                        float areag) {
    float iw = __fadd_rn(__fsub_rn(fminf(a2, g2), fmaxf(a0, g0)), 1.0f);
    float ih = __fadd_rn(__fsub_rn(fminf(a3, g3), fmaxf(a1, g1)), 1.0f);
    iw = fmaxf(iw, 0.0f);
    ih = fmaxf(ih, 0.0f);
    float inter = __fmul_rn(iw, ih);
    float denom = __fsub_rn(__fadd_rn(areaa, areag), inter);
    return __fdiv_rn(inter, denom);
}
__device__ __forceinline__ float area_fn(float x1, float y1, float x2, float y2) {
    return __fmul_rn(__fadd_rn(__fsub_rn(x2, x1), 1.0f),
                     __fadd_rn(__fsub_rn(y2, y1), 1.0f));
}

// ---------------- K0: params + base anchors + bounds + keys (1 block) --------
__global__ void k_setup0(const int* pB, const int* pG, const int* pH, const int* pW) {
    int t = threadIdx.x;
    if (t == 0) {
        int B = *pB, G = *pG, H = *pH, W = *pW;
        if (B > B_MAX) B = B_MAX;
        if (G > G_MAX) G = G_MAX;
        g_p.B = B; g_p.G = G; g_p.H = H; g_p.W = W;
        int KA = H * W * A_NUM;
        if (KA > KA_MAX) KA = KA_MAX;
        g_p.KA = KA;
        const double ratios[3] = {0.5, 1.0, 2.0};
        const double scales[3] = {8.0, 16.0, 32.0};
        int Ntot = 0;
        for (int r = 0; r < 3; r++) {
            double ws = rint(sqrt(256.0 / ratios[r]));
            double hs = rint(ws * ratios[r]);
            for (int s = 0; s < 3; s++) {
                double Wd = ws * scales[s], Hd = hs * scales[s];
                int a = r * 3 + s;
                double x1 = 7.5 - 0.5 * (Wd - 1.0);
                double y1 = 7.5 - 0.5 * (Hd - 1.0);
                double x2 = 7.5 + 0.5 * (Wd - 1.0);
                double y2 = 7.5 + 0.5 * (Hd - 1.0);
                g_abox[a] = make_float4((float)x1, (float)y1, (float)x2, (float)y2);
                int ix1 = (int)llrint(x1), iy1 = (int)llrint(y1);
                int ix2 = (int)llrint(x2), iy2 = (int)llrint(y2);
                int Lx = (ix1 < 0) ? ((-ix1 + 15) / 16) : 0;
                int Ly = (iy1 < 0) ? ((-iy1 + 15) / 16) : 0;
                int nxw = 16 * W - 1 - ix2;
                int nyh = 16 * H - 1 - iy2;
                int Rx = (nxw < 0) ? -1 : min(W - 1, nxw / 16);
                int Ry = (nyh < 0) ? -1 : min(H - 1, nyh / 16);
                g_bnd[a] = make_int4(Lx, Rx, Ly, Ry);
                int nx = Rx - Lx + 1; if (nx < 0) nx = 0;
                int ny = Ry - Ly + 1; if (ny < 0) ny = 0;
                Ntot += nx * ny;
            }
        }
        g_p.N = Ntot;
    }
    if (t < B_MAX) {
        uint32_t h0 = 0u, h1 = (uint32_t)t;
        tf2x32(0u, 42u, h0, h1);
        uint32_t f0 = 0u, f1 = 0u; tf2x32(h0, h1, f0, f1);
        uint32_t c0 = 0u, c1 = 1u; tf2x32(h0, h1, c0, c1);
        g_keyf[t * 2 + 0] = f0; g_keyf[t * 2 + 1] = f1;
        g_keyb[t * 2 + 0] = c0; g_keyb[t * 2 + 1] = c1;
    }
}

// ---------------- K1: analytic rank + anchor compaction + gtmax reset --------
__global__ void k_grid() {
    __shared__ int4 sb[A_NUM];
    __shared__ float4 sbx[A_NUM];
    int tid = threadIdx.x;
    if (tid < A_NUM) { sb[tid] = g_bnd[tid]; sbx[tid] = g_abox[tid]; }
    __syncthreads();
    int ka = blockIdx.x * blockDim.x + tid;
    if (ka < B_MAX * G_MAX) g_gtmax[ka] = 0;
    const int KA = g_p.KA, W = g_p.W;
    if (ka >= KA) return;
    int a = ka % A_NUM;
    int cell = ka / A_NUM;
    int x = cell % W, y = cell / W;
    int rank = 0;
#pragma unroll
    for (int a2 = 0; a2 < A_NUM; a2++) {
        int4 bb = sb[a2];  // {Lx,Rx,Ly,Ry}
        int nx = bb.y - bb.x + 1; if (nx < 0) nx = 0;
        int rb = min(bb.w, y - 1) - bb.z + 1; if (rb < 0) rb = 0;
        rank += rb * nx;
        if (y >= bb.z && y <= bb.w) {
            int xb = min(bb.y, x - 1) - bb.x + 1; if (xb < 0) xb = 0;
            rank += xb;
            if (a2 < a && x >= bb.x && x <= bb.y) rank += 1;
        }
    }
    int4 mb = sb[a];
    bool inside = (x >= mb.x && x <= mb.y && y >= mb.z && y <= mb.w);
    if (inside) {
        float sx = 16.0f * (float)x, sy = 16.0f * (float)y;
        float4 o = sbx[a];
        g_rank[ka] = rank;
        g_anc4[rank] = make_float4(sx + o.x, sy + o.y, sx + o.z, sy + o.w);
    } else {
        g_rank[ka] = -1;
    }
}

// ---------------- K2: fused pass — maxov/arg/gtmax + labels + priority -------
#define APT 4
__global__ void __launch_bounds__(256, 2) k_passA(const float* __restrict__ gt) {
    int b = blockIdx.y;
    if (b >= g_p.B) return;
    const int N = g_p.N, G = g_p.G;
    int base = blockIdx.x * (256 * APT);
    if (base >= N) return;
    __shared__ float4 sgt[G_MAX];
    __shared__ float sga[G_MAX];
    __shared__ int sgmx[G_MAX];
    int tid = threadIdx.x;
    if (tid < G_MAX) {
        float4 gb;
        if (tid < G) gb = reinterpret_cast<const float4*>(gt)[(size_t)b * G + tid];
        else gb = make_float4(2e9f, 2e9f, -2e9f, -2e9f);
        sgt[tid] = gb;
        sga[tid] = area_fn(gb.x, gb.y, gb.z, gb.w);
        sgmx[tid] = 0;
    }
    __syncthreads();
    float4 A[APT]; float area[APT]; float best[APT]; int arg[APT]; bool val[APT];
#pragma unroll
    for (int k = 0; k < APT; k++) {
        int idx = base + k * 256 + tid;
        val[k] = idx < N;
        A[k] = val[k] ? g_anc4[idx] : make_float4(3e9f, 3e9f, -3e9f, -3e9f);
        area[k] = area_fn(A[k].x, A[k].y, A[k].z, A[k].w);
        best[k] = 0.0f; arg[k] = 0;
    }
    float gmax[G_MAX];
#pragma unroll
    for (int g = 0; g < G_MAX; g++) gmax[g] = 0.0f;
#pragma unroll
    for (int g = 0; g < G_MAX; g++) {
        if (g < G) {
            float4 gb = sgt[g]; float ag = sga[g];
            float m = gmax[g];
#pragma unroll
            for (int k = 0; k < APT; k++) {
                float iw = __fadd_rn(__fsub_rn(fminf(A[k].z, gb.z), fmaxf(A[k].x, gb.x)), 1.0f);
                float ih = __fadd_rn(__fsub_rn(fminf(A[k].w, gb.w), fmaxf(A[k].y, gb.y)), 1.0f);
                iw = fmaxf(iw, 0.0f);
                ih = fmaxf(ih, 0.0f);
                float inter = __fmul_rn(iw, ih);
                if (inter > 0.0f) {  // iou == +0 exactly when inter == 0
                    float denom = __fsub_rn(__fadd_rn(area[k], ag), inter);
                    float iou = __fdiv_rn(inter, denom);
                    if (iou > best[k]) { best[k] = iou; arg[k] = g; }
                    m = fmaxf(m, iou);
                }
            }
            gmax[g] = m;
        }
    }
#pragma unroll
    for (int g = 0; g < G_MAX; g++) {
        float v = gmax[g];
#pragma unroll
        for (int off = 16; off > 0; off >>= 1)
            v = fmaxf(v, __shfl_xor_sync(0xFFFFFFFFu, v, off));
        if ((tid & 31) == 0 && v > 0.0f) atomicMax(&sgmx[g], __float_as_int(v));
    }
    __syncthreads();
    if (tid < G) {
        int m = sgmx[tid];
        if (m != 0) atomicMax(&g_gtmax[b * G_MAX + tid], m);
    }
    // epilogue: labels from thresholds + threefry priority (fg or bg key)
    uint32_t kf0 = g_keyf[b * 2], kf1 = g_keyf[b * 2 + 1];
    uint32_t kb0 = g_keyb[b * 2], kb1 = g_keyb[b * 2 + 1];
#pragma unroll
    for (int k = 0; k < APT; k++) {
        if (val[k]) {
            int idx = base + k * 256 + tid;
            signed char lab = -1;
            if (best[k] < 0.3f) lab = 0;
            if (best[k] >= 0.7f) lab = 1;
            g_lab[(size_t)b * N_MAX + idx] = lab;
            g_arg[(size_t)b * N_MAX + idx] = (unsigned char)arg[k];
            if (lab >= 0) {
                uint32_t c0 = 0u, c1 = (uint32_t)idx;
                if (lab == 1) tf2x32(kf0, kf1, c0, c1);
                else          tf2x32(kb0, kb1, c0, c1);
                g_prio[(size_t)b * N_MAX + idx] = (c0 ^ c1) >> 9;
            }
        }
    }
}

// ---------------- K3: per-gt argmax-hit promotion (windowed) -----------------
__global__ void k_hit(const float* __restrict__ gt) {
    int g = blockIdx.x, b = blockIdx.y;
    if (b >= g_p.B || g >= g_p.G) return;
    float gm = __int_as_float(g_gtmax[b * G_MAX + g]);
    if (!(gm > 0.0f)) return;
    const int W = g_p.W;
    const float4 gb = reinterpret_cast<const float4*>(gt)[(size_t)b * g_p.G + g];
    float areag = area_fn(gb.x, gb.y, gb.z, gb.w);
    uint32_t kf0 = g_keyf[b * 2], kf1 = g_keyf[b * 2 + 1];
    int tid = threadIdx.x;
    for (int a = 0; a < A_NUM; a++) {
        float4 o = g_abox[a];
        int4 bb = g_bnd[a];
        // overlap window (with slack): 16x+o.z > gb.x-1  and  16x+o.x < gb.z+1
        int xlo = max(bb.x, (int)floorf((gb.x - 2.0f - o.z) * 0.0625f));
        int xhi = min(bb.y, (int)ceilf((gb.z + 2.0f - o.x) * 0.0625f));
        int ylo = max(bb.z, (int)floorf((gb.y - 2.0f - o.w) * 0.0625f));
        int yhi = min(bb.w, (int)ceilf((gb.w + 2.0f - o.y) * 0.0625f));
        int nx = xhi - xlo + 1, ny = yhi - ylo + 1;
        if (nx <= 0 || ny <= 0) continue;
        int total = nx * ny;
        for (int t = tid; t < total; t += blockDim.x) {
            int x = xlo + t % nx;
            int y = ylo + t / nx;
            float sx = 16.0f * (float)x, sy = 16.0f * (float)y;
            float a0 = sx + o.x, a1 = sy + o.y, a2 = sx + o.z, a3 = sy + o.w;
            float areaa = area_fn(a0, a1, a2, a3);
            float iou = iou_fn(a0, a1, a2, a3, areaa, gb.x, gb.y, gb.z, gb.w, areag);
            if (iou == gm) {
                int rank = g_rank[(y * W + x) * A_NUM + a];
                if (rank >= 0) {
                    g_lab[(size_t)b * N_MAX + rank] = 1;
                    uint32_t c0 = 0u, c1 = (uint32_t)rank;
                    tf2x32(kf0, kf1, c0, c1);
                    g_prio[(size_t)b * N_MAX + rank] = (c0 ^ c1) >> 9;
                }
            }
        }
    }
}

// ---------------- K4: 2-stage exact k-th-smallest + label rewrite ------------
#define SEL_BUF 1024
__device__ unsigned long long select_kth(const uint32_t* __restrict__ prio,
                                         const signed char* __restrict__ lab,
                                         signed char want, int N, int kk,
                                         int* hist, unsigned long long* buf,
                                         int* s_i, unsigned long long* s_thr) {
    int tid = threadIdx.x;
    for (int j = tid; j < 256; j += blockDim.x) hist[j] = 0;
    if (tid == 0) { s_i[0] = 0; }
    __syncthreads();
    for (int i = tid; i < N; i += blockDim.x)
        if (lab[i] == want) atomicAdd(&hist[prio[i] >> 15], 1);
    __syncthreads();
    if (tid == 0) {
        int cum = 0, d = 0;
        for (; d < 256; d++) {
            int c = hist[d];
            if (cum + c >= kk) break;
            cum += c;
        }
        s_i[1] = d;
        s_i[2] = kk - cum;
    }
    __syncthreads();
    int d = s_i[1], lk = s_i[2];
    for (int i = tid; i < N; i += blockDim.x) {
        if (lab[i] == want && (int)(prio[i] >> 15) == d) {
            int pos = atomicAdd(&s_i[0], 1);
            if (pos < SEL_BUF)
                buf[pos] = ((unsigned long long)prio[i] << 16) | (unsigned)i;
        }
    }
    __syncthreads();
    int m = min(s_i[0], SEL_BUF);
    if (tid < m) {
        unsigned long long key = buf[tid];
        int c = 0;
        for (int j = 0; j < m; j++) c += (buf[j] < key);
        if (c == lk - 1) *s_thr = key;
    }
    __syncthreads();
    unsigned long long r = *s_thr;
    __syncthreads();
    return r;
}

__global__ void k_select() {
    int b = blockIdx.x;
    if (b >= g_p.B) return;
    const int N = g_p.N;
    signed char* lab = g_lab + (size_t)b * N_MAX;
    const uint32_t* prio = g_prio + (size_t)b * N_MAX;
    __shared__ int hist[256];
    __shared__ unsigned long long buf[SEL_BUF];
    __shared__ int s_i[4];
    __shared__ unsigned long long s_thr;
    __shared__ int s_fg, s_bg;
    int tid = threadIdx.x;
    if (tid == 0) { s_fg = 0; s_bg = 0; }
    __syncthreads();
    int fg = 0, bg = 0;
    for (int i = tid; i < N; i += blockDim.x) {
        signed char l = lab[i];
        fg += (l == 1);
        bg += (l == 0);
    }
    atomicAdd(&s_fg, fg);
    atomicAdd(&s_bg, bg);
    __syncthreads();
    int fgcnt = s_fg, bgcnt = s_bg;
    unsigned long long fthr = ~0ull, bthr = ~0ull;
    if (fgcnt > 128) {
        if (tid == 0) s_thr = ~0ull;
        __syncthreads();
        fthr = select_kth(prio, lab, 1, N, 128, hist, buf, s_i, &s_thr);
    }
    int numbg = 256 - (fgcnt < 128 ? fgcnt : 128);
    if (bgcnt > numbg) {
        if (tid == 0) s_thr = ~0ull;
        __syncthreads();
        bthr = select_kth(prio, lab, 0, N, numbg, hist, buf, s_i, &s_thr);
    }
    __syncthreads();
    for (int i = tid; i < N; i += blockDim.x) {
        signed char l = lab[i];
        if (l == 1 || l == 0) {
            unsigned long long key = ((unsigned long long)prio[i] << 16) | (unsigned)i;
            unsigned long long thr = (l == 1) ? fthr : bthr;
            if (key > thr) lab[i] = -1;
        }
    }
}

// ---------------- K5: emit labels [B,9,H,W] + reg [B,36,H,W] -----------------
__global__ void k_emit(const float* __restrict__ gt, float* __restrict__ out) {
    int b = blockIdx.y;
    if (b >= g_p.B) return;
    const int H = g_p.H, W = g_p.W, HW = H * W, KA = g_p.KA, G = g_p.G, B = g_p.B;
    int t = blockIdx.x * blockDim.x + threadIdx.x;
    if (t >= KA) return;
    int a = t / HW;
    int rem = t - a * HW;
    int ka = rem * A_NUM + a;
    int rank = g_rank[ka];
    float lv = -1.0f;
    float r0 = 0.f, r1 = 0.f, r2 = 0.f, r3 = 0.f;
    if (rank >= 0) {
        signed char l = g_lab[(size_t)b * N_MAX + rank];
        lv = (float)l;
        if (l == 1) {
            int arg = g_arg[(size_t)b * N_MAX + rank];
            float4 av = g_anc4[rank];
            const float* gp = gt + ((size_t)b * G + arg) * 4;
            float g0 = gp[0], g1 = gp[1], g2 = gp[2], g3 = gp[3];
            float aw = av.z - av.x + 1.0f, ah = av.w - av.y + 1.0f;
            float acx = av.x + 0.5f * (aw - 1.0f), acy = av.y + 0.5f * (ah - 1.0f);
            float gw = g2 - g0 + 1.0f, gh = g3 - g1 + 1.0f;
            float gcx = g0 + 0.5f * (gw - 1.0f), gcy = g1 + 0.5f * (gh - 1.0f);
            r0 = (gcx - acx) / aw;
            r1 = (gcy - acy) / ah;
            r2 = logf(gw / aw);
            r3 = logf(gh / ah);
        }
    }
    out[((size_t)b * A_NUM + a) * HW + rem] = lv;
    float* out_reg = out + (size_t)B * A_NUM * HW;
    size_t rb = ((size_t)b * A_NUM * 4 + (size_t)a * 4) * HW + rem;
    out_reg[rb] = r0;
    out_reg[rb + HW] = r1;
    out_reg[rb + 2 * (size_t)HW] = r2;
    out_reg[rb + 3 * (size_t)HW] = r3;
}

extern "C" void kernel_launch(void* const* d_in, const int* in_sizes, int n_in,
                              void* d_out, int out_size) {
    const float* gt = (const float*)d_in[0];
    const int* pB = (const int*)d_in[1];
    const int* pG = (const int*)d_in[2];
    const int* pH = (const int*)d_in[3];
    const int* pW = (const int*)d_in[4];

    k_setup0<<<1, 64>>>(pB, pG, pH, pW);
    k_grid<<<(KA_MAX + 255) / 256, 256>>>();
    {
        dim3 g((N_MAX + 256 * APT - 1) / (256 * APT), B_MAX);
        k_passA<<<g, 256>>>(gt);
    }
    {
        dim3 g(G_MAX, B_MAX);
        k_hit<<<g, 128>>>(gt);
    }
    k_select<<<B_MAX, 1024>>>();
    {
        dim3 g((KA_MAX + 255) / 256, B_MAX);
        k_emit<<<g, 256>>>(gt, (float*)d_out);
    }
}

// round 8
// speedup vs baseline: 2.8557x; 1.4282x over previous
#include <cuda_runtime.h>
#include <cstdint>
#include <math_constants.h>

#define A_NUM 9
#define KA_MAX 36864   // 64*64*9
#define N_MAX  36864
#define B_MAX  32
#define G_MAX  64

struct Params { int B, G, H, W, KA, N; };
__device__ Params g_p;
__device__ int    g_rank_t[KA_MAX];          // [a][cell] inside rank or -1
__device__ float4 g_anc4[N_MAX];             // inside anchor boxes
__device__ float4 g_abox[A_NUM];             // base anchor offsets
__device__ int4   g_bnd[A_NUM];              // {Lx,Rx,Ly,Ry} valid cell ranges
__device__ uint32_t g_keyf[B_MAX * 2];
__device__ uint32_t g_keyb[B_MAX * 2];
__device__ int    g_gtmax[B_MAX * G_MAX];    // float bits, atomicMax as int (iou>=0)
__device__ unsigned char g_arg[B_MAX * N_MAX];
__device__ signed char g_lab[B_MAX * N_MAX];
__device__ uint32_t g_prio[B_MAX * N_MAX];   // 23-bit priority (fg or bg, exclusive)

// ---------------- Threefry-2x32 (JAX schedule) -------------------------------
__device__ __forceinline__ uint32_t rotl32(uint32_t x, uint32_t r) {
    return __funnelshift_l(x, x, r);
}
__device__ __forceinline__ void tf2x32(uint32_t k0, uint32_t k1,
                                       uint32_t& x0, uint32_t& x1) {
    uint32_t ks2 = k0 ^ k1 ^ 0x1BD11BDAu;
    x0 += k0; x1 += k1;
    const uint32_t rA[4] = {13u, 15u, 26u, 6u};
    const uint32_t rB[4] = {17u, 29u, 16u, 24u};
#pragma unroll
    for (int i = 0; i < 4; i++) { x0 += x1; x1 = rotl32(x1, rA[i]); x1 ^= x0; }
    x0 += k1; x1 += ks2 + 1u;
#pragma unroll
    for (int i = 0; i < 4; i++) { x0 += x1; x1 = rotl32(x1, rB[i]); x1 ^= x0; }
    x0 += ks2; x1 += k0 + 2u;
#pragma unroll
    for (int i = 0; i < 4; i++) { x0 += x1; x1 = rotl32(x1, rA[i]); x1 ^= x0; }
    x0 += k0; x1 += k1 + 3u;
#pragma unroll
    for (int i = 0; i < 4; i++) { x0 += x1; x1 = rotl32(x1, rB[i]); x1 ^= x0; }
    x0 += k1; x1 += ks2 + 4u;
#pragma unroll
    for (int i = 0; i < 4; i++) { x0 += x1; x1 = rotl32(x1, rA[i]); x1 ^= x0; }
    x0 += ks2; x1 += k0 + 5u;
}

// ---------------- IoU (identical op order everywhere; no FMA contraction) ----
__device__ __forceinline__ float iou_fn(float a0, float a1, float a2, float a3,
                                        float areaa,
                                        float g0, float g1, float g2, float g3,
                                        float areag) {
    float iw = __fadd_rn(__fsub_rn(fminf(a2, g2), fmaxf(a0, g0)), 1.0f);
    float ih = __fadd_rn(__fsub_rn(fminf(a3, g3), fmaxf(a1, g1)), 1.0f);
    iw = fmaxf(iw, 0.0f);
    ih = fmaxf(ih, 0.0f);
    float inter = __fmul_rn(iw, ih);
    float denom = __fsub_rn(__fadd_rn(areaa, areag), inter);
    return __fdiv_rn(inter, denom);
}
__device__ __forceinline__ float area_fn(float x1, float y1, float x2, float y2) {
    return __fmul_rn(__fadd_rn(__fsub_rn(x2, x1), 1.0f),
                     __fadd_rn(__fsub_rn(y2, y1), 1.0f));
}

// ---- base anchors + bounds computed per block (cheap, double precision) -----
__device__ __forceinline__ void compute_anchors(int H, int W,
                                                float4* sbx, int4* sb, int* Ntot) {
    const double ratios[3] = {0.5, 1.0, 2.0};
    const double scales[3] = {8.0, 16.0, 32.0};
    int nt = 0;
    for (int r = 0; r < 3; r++) {
        double ws = rint(sqrt(256.0 / ratios[r]));
        double hs = rint(ws * ratios[r]);
        for (int s = 0; s < 3; s++) {
            double Wd = ws * scales[s], Hd = hs * scales[s];
            int a = r * 3 + s;
            double x1 = 7.5 - 0.5 * (Wd - 1.0);
            double y1 = 7.5 - 0.5 * (Hd - 1.0);
            double x2 = 7.5 + 0.5 * (Wd - 1.0);
            double y2 = 7.5 + 0.5 * (Hd - 1.0);
            sbx[a] = make_float4((float)x1, (float)y1, (float)x2, (float)y2);
            int ix1 = (int)llrint(x1), iy1 = (int)llrint(y1);
            int ix2 = (int)llrint(x2), iy2 = (int)llrint(y2);
            int Lx = (ix1 < 0) ? ((-ix1 + 15) / 16) : 0;
            int Ly = (iy1 < 0) ? ((-iy1 + 15) / 16) : 0;
            int nxw = 16 * W - 1 - ix2;
            int nyh = 16 * H - 1 - iy2;
            int Rx = (nxw < 0) ? -1 : min(W - 1, nxw / 16);
            int Ry = (nyh < 0) ? -1 : min(H - 1, nyh / 16);
            sb[a] = make_int4(Lx, Rx, Ly, Ry);
            int nx = Rx - Lx + 1; if (nx < 0) nx = 0;
            int ny = Ry - Ly + 1; if (ny < 0) ny = 0;
            nt += nx * ny;
        }
    }
    *Ntot = nt;
}

// ---------------- K1: setup + analytic rank + compaction + resets ------------
__global__ void k_grid(const int* pB, const int* pG, const int* pH, const int* pW) {
    __shared__ int4 sb[A_NUM];
    __shared__ float4 sbx[A_NUM];
    __shared__ int sdim[3];  // H, W, KA
    int tid = threadIdx.x;
    if (tid == 0) {
        int H = *pH, W = *pW;
        int Ntot;
        compute_anchors(H, W, sbx, sb, &Ntot);
        int KA = H * W * A_NUM;
        if (KA > KA_MAX) KA = KA_MAX;
        sdim[0] = H; sdim[1] = W; sdim[2] = KA;
        if (blockIdx.x == 0) {
            int B = *pB, G = *pG;
            if (B > B_MAX) B = B_MAX;
            if (G > G_MAX) G = G_MAX;
            Params p; p.B = B; p.G = G; p.H = H; p.W = W; p.KA = KA; p.N = Ntot;
            g_p = p;
            for (int a = 0; a < A_NUM; a++) { g_abox[a] = sbx[a]; g_bnd[a] = sb[a]; }
        }
    }
    __syncthreads();
    if (blockIdx.x == 0 && tid < B_MAX) {
        uint32_t h0 = 0u, h1 = (uint32_t)tid;
        tf2x32(0u, 42u, h0, h1);
        uint32_t f0 = 0u, f1 = 0u; tf2x32(h0, h1, f0, f1);
        uint32_t c0 = 0u, c1 = 1u; tf2x32(h0, h1, c0, c1);
        g_keyf[tid * 2 + 0] = f0; g_keyf[tid * 2 + 1] = f1;
        g_keyb[tid * 2 + 0] = c0; g_keyb[tid * 2 + 1] = c1;
    }
    int ka = blockIdx.x * blockDim.x + tid;
    if (ka < B_MAX * G_MAX) g_gtmax[ka] = 0;
    const int W = sdim[1], KA = sdim[2];
    const int HW = sdim[0] * W;
    if (ka >= KA) return;
    int a = ka % A_NUM;
    int cell = ka / A_NUM;
    int x = cell % W, y = cell / W;
    int rank = 0;
#pragma unroll
    for (int a2 = 0; a2 < A_NUM; a2++) {
        int4 bb = sb[a2];  // {Lx,Rx,Ly,Ry}
        int nx = bb.y - bb.x + 1; if (nx < 0) nx = 0;
        int rb = min(bb.w, y - 1) - bb.z + 1; if (rb < 0) rb = 0;
        rank += rb * nx;
        if (y >= bb.z && y <= bb.w) {
            int xb = min(bb.y, x - 1) - bb.x + 1; if (xb < 0) xb = 0;
            rank += xb;
            if (a2 < a && x >= bb.x && x <= bb.y) rank += 1;
        }
    }
    int4 mb = sb[a];
    bool inside = (x >= mb.x && x <= mb.y && y >= mb.z && y <= mb.w);
    if (inside) {
        float sx = 16.0f * (float)x, sy = 16.0f * (float)y;
        float4 o = sbx[a];
        g_anc4[rank] = make_float4(sx + o.x, sy + o.y, sx + o.z, sy + o.w);
        g_rank_t[a * HW + cell] = rank;
    } else {
        g_rank_t[a * HW + cell] = -1;
    }
}

// ---------------- K2: fused pass — maxov/arg/gtmax + labels + priority -------
#define APT 4
__global__ void k_passA(const float* __restrict__ gt) {
    int b = blockIdx.y;
    if (b >= g_p.B) return;
    const int N = g_p.N, G = g_p.G;
    int base = blockIdx.x * (256 * APT);
    if (base >= N) return;
    __shared__ float4 sgt[G_MAX];
    __shared__ float sga[G_MAX];
    __shared__ int sgmx[G_MAX];
    int tid = threadIdx.x;
    if (tid < G_MAX) {
        float4 gb;
        if (tid < G) gb = reinterpret_cast<const float4*>(gt)[(size_t)b * G + tid];
        else gb = make_float4(2e9f, 2e9f, -2e9f, -2e9f);
        sgt[tid] = gb;
        sga[tid] = area_fn(gb.x, gb.y, gb.z, gb.w);
        sgmx[tid] = 0;
    }
    __syncthreads();
    float4 A[APT]; float area[APT]; float best[APT]; int arg[APT]; bool val[APT];
#pragma unroll
    for (int k = 0; k < APT; k++) {
        int idx = base + k * 256 + tid;
        val[k] = idx < N;
        A[k] = val[k] ? g_anc4[idx] : make_float4(3e9f, 3e9f, -3e9f, -3e9f);
        area[k] = area_fn(A[k].x, A[k].y, A[k].z, A[k].w);
        best[k] = 0.0f; arg[k] = 0;
    }
#pragma unroll
    for (int g = 0; g < G_MAX; g++) {
        if (g < G) {
            float4 gb = sgt[g]; float ag = sga[g];
            float m = 0.0f;
#pragma unroll
            for (int k = 0; k < APT; k++) {
                float iw = __fadd_rn(__fsub_rn(fminf(A[k].z, gb.z), fmaxf(A[k].x, gb.x)), 1.0f);
                float ih = __fadd_rn(__fsub_rn(fminf(A[k].w, gb.w), fmaxf(A[k].y, gb.y)), 1.0f);
                iw = fmaxf(iw, 0.0f);
                ih = fmaxf(ih, 0.0f);
                float inter = __fmul_rn(iw, ih);
                if (inter > 0.0f) {  // iou == +0 exactly when inter == 0
                    float denom = __fsub_rn(__fadd_rn(area[k], ag), inter);
                    float iou = __fdiv_rn(inter, denom);
                    if (iou > best[k]) { best[k] = iou; arg[k] = g; }
                    m = fmaxf(m, iou);
                }
            }
#pragma unroll
            for (int off = 16; off > 0; off >>= 1)
                m = fmaxf(m, __shfl_xor_sync(0xFFFFFFFFu, m, off));
            if ((tid & 31) == 0 && m > 0.0f) atomicMax(&sgmx[g], __float_as_int(m));
        }
    }
    __syncthreads();
    if (tid < G) {
        int m = sgmx[tid];
        if (m != 0) atomicMax(&g_gtmax[b * G_MAX + tid], m);
    }
    // epilogue: labels from thresholds + threefry priority (fg or bg key)
    uint32_t kf0 = g_keyf[b * 2], kf1 = g_keyf[b * 2 + 1];
    uint32_t kb0 = g_keyb[b * 2], kb1 = g_keyb[b * 2 + 1];
#pragma unroll
    for (int k = 0; k < APT; k++) {
        if (val[k]) {
            int idx = base + k * 256 + tid;
            signed char lab = -1;
            if (best[k] < 0.3f) lab = 0;
            if (best[k] >= 0.7f) lab = 1;
            g_lab[(size_t)b * N_MAX + idx] = lab;
            g_arg[(size_t)b * N_MAX + idx] = (unsigned char)arg[k];
            if (lab >= 0) {
                uint32_t q0 = (lab == 1) ? kf0 : kb0;
                uint32_t q1 = (lab == 1) ? kf1 : kb1;
                uint32_t c0 = 0u, c1 = (uint32_t)idx;
                tf2x32(q0, q1, c0, c1);
                g_prio[(size_t)b * N_MAX + idx] = (c0 ^ c1) >> 9;
            }
        }
    }
}

// ---------------- K3: per-gt argmax-hit promotion (tight windows) ------------
__global__ void k_hit(const float* __restrict__ gt) {
    int g = blockIdx.x, b = blockIdx.y;
    if (b >= g_p.B || g >= g_p.G) return;
    float gm = __int_as_float(g_gtmax[b * G_MAX + g]);
    if (!(gm > 0.0f)) return;
    const int W = g_p.W;
    const int HW = g_p.H * W;
    const float4 gb = reinterpret_cast<const float4*>(gt)[(size_t)b * g_p.G + g];
    float areag = area_fn(gb.x, gb.y, gb.z, gb.w);
    float gw = gb.z - gb.x + 1.0f, gh = gb.w - gb.y + 1.0f;
    __shared__ int s_xlo[A_NUM], s_nx[A_NUM], s_ylo[A_NUM];
    __shared__ int s_off[A_NUM + 1];
    int tid = threadIdx.x;
    if (tid < A_NUM) {
        float4 o = g_abox[tid];
        int4 bb = g_bnd[tid];
        float aw = o.z - o.x + 1.0f, ah = o.w - o.y + 1.0f;
        float areaa = __fmul_rn(aw, ah);
        // necessary: inter >= T = gm/(1+gm)*(areaa+areag), inter <= min(areas)
        float T = (gm / (1.0f + gm)) * (areaa + areag);
        int xlo = 0, ylo = 0, nx = 0, ny = 0;
        if (T <= fminf(areaa, areag) + 4.0f) {
            float wxr = fmaxf(T / fminf(ah, gh) - 4.0f, 1.0f);  // iw >= wxr
            float wyr = fmaxf(T / fminf(aw, gw) - 4.0f, 1.0f);  // ih >= wyr
            xlo = max(bb.x, (int)ceilf((gb.x + wxr - 1.0f - o.z) * 0.0625f));
            int xhi = min(bb.y, (int)floorf((gb.z - wxr + 1.0f - o.x) * 0.0625f));
            ylo = max(bb.z, (int)ceilf((gb.y + wyr - 1.0f - o.w) * 0.0625f));
            int yhi = min(bb.w, (int)floorf((gb.w - wyr + 1.0f - o.y) * 0.0625f));
            nx = xhi - xlo + 1; if (nx < 0) nx = 0;
            ny = yhi - ylo + 1; if (ny < 0) ny = 0;
        }
        s_xlo[tid] = xlo; s_ylo[tid] = ylo; s_nx[tid] = nx;
        s_off[tid + 1] = nx * ny;  // filled as counts, prefixed below
    }
    __syncthreads();
    if (tid == 0) {
        s_off[0] = 0;
        for (int a = 0; a < A_NUM; a++) s_off[a + 1] += s_off[a];
    }
    __syncthreads();
    int total = s_off[A_NUM];
    uint32_t kf0 = g_keyf[b * 2], kf1 = g_keyf[b * 2 + 1];
    for (int t = tid; t < total; t += blockDim.x) {
        int a = 0;
        while (t >= s_off[a + 1]) a++;
        int u = t - s_off[a];
        int nx = s_nx[a];
        int x = s_xlo[a] + u % nx;
        int y = s_ylo[a] + u / nx;
        float4 o = g_abox[a];
        float sx = 16.0f * (float)x, sy = 16.0f * (float)y;
        float a0 = sx + o.x, a1 = sy + o.y, a2 = sx + o.z, a3 = sy + o.w;
        float areaa = area_fn(a0, a1, a2, a3);
        float iou = iou_fn(a0, a1, a2, a3, areaa, gb.x, gb.y, gb.z, gb.w, areag);
        if (iou == gm) {
            int rank = g_rank_t[a * HW + y * W + x];
            if (rank >= 0) {
                g_lab[(size_t)b * N_MAX + rank] = 1;
                uint32_t c0 = 0u, c1 = (uint32_t)rank;
                tf2x32(kf0, kf1, c0, c1);
                g_prio[(size_t)b * N_MAX + rank] = (c0 ^ c1) >> 9;
            }
        }
    }
}

// ---------------- K4: 3-pass exact subsample (hist -> gather -> rewrite) -----
#define SELB 512
__global__ void k_select() {
    int b = blockIdx.x;
    if (b >= g_p.B) return;
    const int N = g_p.N;
    signed char* lab = g_lab + (size_t)b * N_MAX;
    const uint32_t* prio = g_prio + (size_t)b * N_MAX;
    __shared__ int hf[256], hb[256];
    __shared__ unsigned long long buff[SELB], bufb[SELB];
    __shared__ int s_cf, s_cb;
    __shared__ int s_dat[6];
    __shared__ unsigned long long s_fthr, s_bthr;
    int tid = threadIdx.x;
    if (tid < 256) { hf[tid] = 0; hb[tid] = 0; }
    if (tid == 0) { s_cf = 0; s_cb = 0; s_fthr = ~0ull; s_bthr = ~0ull; }
    __syncthreads();
    for (int i = tid; i < N; i += blockDim.x) {
        signed char l = lab[i];
        if (l >= 0) {
            int bin = prio[i] >> 15;
            atomicAdd((l == 1) ? &hf[bin] : &hb[bin], 1);
        }
    }
    __syncthreads();
    if (tid == 0) {
        int fg = 0, bg = 0;
        for (int j = 0; j < 256; j++) { fg += hf[j]; bg += hb[j]; }
        int needf = fg > 128, df = 0, lkf = 0;
        if (needf) {
            int cum = 0, d = 0;
            for (; d < 256; d++) { int c = hf[d]; if (cum + c >= 128) break; cum += c; }
            df = d; lkf = 128 - cum;
        }
        int numbg = 256 - (fg < 128 ? fg : 128);
        int needb = bg > numbg, db = 0, lkb = 0;
        if (needb) {
            int cum = 0, d = 0;
            for (; d < 256; d++) { int c = hb[d]; if (cum + c >= numbg) break; cum += c; }
            db = d; lkb = numbg - cum;
        }
        s_dat[0] = needf; s_dat[1] = df; s_dat[2] = lkf;
        s_dat[3] = needb; s_dat[4] = db; s_dat[5] = lkb;
    }
    __syncthreads();
    int needf = s_dat[0], df = s_dat[1], lkf = s_dat[2];
    int needb = s_dat[3], db = s_dat[4], lkb = s_dat[5];
    if (needf || needb) {
        for (int i = tid; i < N; i += blockDim.x) {
            signed char l = lab[i];
            if (l < 0) continue;
            uint32_t p = prio[i];
            int bin = p >> 15;
            if (l == 1) {
                if (needf && bin == df) {
                    int pos = atomicAdd(&s_cf, 1);
                    if (pos < SELB) buff[pos] = ((unsigned long long)p << 16) | (unsigned)i;
                }
            } else {
                if (needb && bin == db) {
                    int pos = atomicAdd(&s_cb, 1);
                    if (pos < SELB) bufb[pos] = ((unsigned long long)p << 16) | (unsigned)i;
                }
            }
        }
        __syncthreads();
        int mf = min(s_cf, SELB), mb = min(s_cb, SELB);
        if (needf && tid < mf) {
            unsigned long long key = buff[tid];
            int c = 0;
            for (int j = 0; j < mf; j++) c += (buff[j] < key);
            if (c == lkf - 1) s_fthr = key;
        }
        if (needb && tid < mb) {
            unsigned long long key = bufb[tid];
            int c = 0;
            for (int j = 0; j < mb; j++) c += (bufb[j] < key);
            if (c == lkb - 1) s_bthr = key;
        }
        __syncthreads();
    }
    unsigned long long fthr = s_fthr, bthr = s_bthr;
    for (int i = tid; i < N; i += blockDim.x) {
        signed char l = lab[i];
        if (l >= 0) {
            unsigned long long key = ((unsigned long long)prio[i] << 16) | (unsigned)i;
            if (key > ((l == 1) ? fthr : bthr)) lab[i] = -1;
        }
    }
}

// ---------------- K5: emit labels [B,9,H,W] + reg [B,36,H,W] -----------------
__global__ void k_emit(const float* __restrict__ gt, float* __restrict__ out) {
    int b = blockIdx.y;
    if (b >= g_p.B) return;
    const int H = g_p.H, W = g_p.W, HW = H * W, KA = g_p.KA, G = g_p.G, B = g_p.B;
    int t = blockIdx.x * blockDim.x + threadIdx.x;  // linear over (a, y, x)
    if (t >= KA) return;
    int a = t / HW;
    int rem = t - a * HW;
    int rank = g_rank_t[t];   // transposed layout: coalesced
    float lv = -1.0f;
    float r0 = 0.f, r1 = 0.f, r2 = 0.f, r3 = 0.f;
    if (rank >= 0) {
        signed char l = g_lab[(size_t)b * N_MAX + rank];
        lv = (float)l;
        if (l == 1) {
            int arg = g_arg[(size_t)b * N_MAX + rank];
            float4 av = g_anc4[rank];
            const float* gp = gt + ((size_t)b * G + arg) * 4;
            float g0 = gp[0], g1 = gp[1], g2 = gp[2], g3 = gp[3];
            float aw = av.z - av.x + 1.0f, ah = av.w - av.y + 1.0f;
            float acx = av.x + 0.5f * (aw - 1.0f), acy = av.y + 0.5f * (ah - 1.0f);
            float gw = g2 - g0 + 1.0f, gh = g3 - g1 + 1.0f;
            float gcx = g0 + 0.5f * (gw - 1.0f), gcy = g1 + 0.5f * (gh - 1.0f);
            r0 = (gcx - acx) / aw;
            r1 = (gcy - acy) / ah;
            r2 = logf(gw / aw);
            r3 = logf(gh / ah);
        }
    }
    out[((size_t)b * A_NUM + a) * HW + rem] = lv;
    float* out_reg = out + (size_t)B * A_NUM * HW;
    size_t rb = ((size_t)b * A_NUM * 4 + (size_t)a * 4) * HW + rem;
    out_reg[rb] = r0;
    out_reg[rb + HW] = r1;
    out_reg[rb + 2 * (size_t)HW] = r2;
    out_reg[rb + 3 * (size_t)HW] = r3;
}

extern "C" void kernel_launch(void* const* d_in, const int* in_sizes, int n_in,
                              void* d_out, int out_size) {
    const float* gt = (const float*)d_in[0];
    const int* pB = (const int*)d_in[1];
    const int* pG = (const int*)d_in[2];
    const int* pH = (const int*)d_in[3];
    const int* pW = (const int*)d_in[4];

    k_grid<<<(KA_MAX + 255) / 256, 256>>>(pB, pG, pH, pW);
    {
        dim3 g((N_MAX + 256 * APT - 1) / (256 * APT), B_MAX);
        k_passA<<<g, 256>>>(gt);
    }
    {
        dim3 g(G_MAX, B_MAX);
        k_hit<<<g, 128>>>(gt);
    }
    k_select<<<B_MAX, 1024>>>();
    {
        dim3 g((KA_MAX + 255) / 256, B_MAX);
        k_emit<<<g, 256>>>(gt, (float*)d_out);
    }
}

// round 9
// speedup vs baseline: 3.2714x; 1.1456x over previous
#include <cuda_runtime.h>
#include <cstdint>
#include <math_constants.h>

#define A_NUM 9
#define KA_MAX 36864   // 64*64*9
#define N_MAX  36864
#define B_MAX  32
#define G_MAX  64
#define SELB   512

struct Params { int B, G, H, W, KA, N; };
__device__ Params g_p;
__device__ int    g_rank_t[KA_MAX];          // [a][cell] inside rank or -1
__device__ float4 g_anc4[N_MAX];             // inside anchor boxes
__device__ float4 g_abox[A_NUM];             // base anchor offsets
__device__ int4   g_bnd[A_NUM];              // {Lx,Rx,Ly,Ry} valid cell ranges
__device__ uint32_t g_keyf[B_MAX * 2];
__device__ uint32_t g_keyb[B_MAX * 2];
__device__ int    g_gtmax[B_MAX * G_MAX];    // float bits, atomicMax as int (iou>=0)
__device__ unsigned char g_arg[B_MAX * N_MAX];
__device__ int    g_lab[B_MAX * N_MAX];      // int for atomicExch in k_hit
__device__ uint32_t g_prio[B_MAX * N_MAX];   // 23-bit priority (fg or bg, exclusive)
__device__ int    g_hist[B_MAX][2][256];     // [img][fg/bg][bin]
__device__ int    g_seldat[B_MAX][6];        // needf, df, lkf, needb, db, lkb
__device__ unsigned long long g_cand[B_MAX][2][SELB];
__device__ int    g_candcnt[B_MAX][2];
__device__ unsigned long long g_thr[B_MAX][2];

// ---------------- Threefry-2x32 (JAX schedule) -------------------------------
__device__ __forceinline__ uint32_t rotl32(uint32_t x, uint32_t r) {
    return __funnelshift_l(x, x, r);
}
__device__ __forceinline__ void tf2x32(uint32_t k0, uint32_t k1,
                                       uint32_t& x0, uint32_t& x1) {
    uint32_t ks2 = k0 ^ k1 ^ 0x1BD11BDAu;
    x0 += k0; x1 += k1;
    const uint32_t rA[4] = {13u, 15u, 26u, 6u};
    const uint32_t rB[4] = {17u, 29u, 16u, 24u};
#pragma unroll
    for (int i = 0; i < 4; i++) { x0 += x1; x1 = rotl32(x1, rA[i]); x1 ^= x0; }
    x0 += k1; x1 += ks2 + 1u;
#pragma unroll
    for (int i = 0; i < 4; i++) { x0 += x1; x1 = rotl32(x1, rB[i]); x1 ^= x0; }
    x0 += ks2; x1 += k0 + 2u;
#pragma unroll
    for (int i = 0; i < 4; i++) { x0 += x1; x1 = rotl32(x1, rA[i]); x1 ^= x0; }
    x0 += k0; x1 += k1 + 3u;
#pragma unroll
    for (int i = 0; i < 4; i++) { x0 += x1; x1 = rotl32(x1, rB[i]); x1 ^= x0; }
    x0 += k1; x1 += ks2 + 4u;
#pragma unroll
    for (int i = 0; i < 4; i++) { x0 += x1; x1 = rotl32(x1, rA[i]); x1 ^= x0; }
    x0 += ks2; x1 += k0 + 5u;
}

// ---------------- IoU (identical op order everywhere; no FMA contraction) ----
__device__ __forceinline__ float iou_fn(float a0, float a1, float a2, float a3,
                                        float areaa,
                                        float g0, float g1, float g2, float g3,
                                        float areag) {
    float iw = __fadd_rn(__fsub_rn(fminf(a2, g2), fmaxf(a0, g0)), 1.0f);
    float ih = __fadd_rn(__fsub_rn(fminf(a3, g3), fmaxf(a1, g1)), 1.0f);
    iw = fmaxf(iw, 0.0f);
    ih = fmaxf(ih, 0.0f);
    float inter = __fmul_rn(iw, ih);
    float denom = __fsub_rn(__fadd_rn(areaa, areag), inter);
    return __fdiv_rn(inter, denom);
}
__device__ __forceinline__ float area_fn(float x1, float y1, float x2, float y2) {
    return __fmul_rn(__fadd_rn(__fsub_rn(x2, x1), 1.0f),
                     __fadd_rn(__fsub_rn(y2, y1), 1.0f));
}

// ---- base anchors + bounds computed per block (cheap, double precision) -----
__device__ __forceinline__ void compute_anchors(int H, int W,
                                                float4* sbx, int4* sb, int* Ntot) {
    const double ratios[3] = {0.5, 1.0, 2.0};
    const double scales[3] = {8.0, 16.0, 32.0};
    int nt = 0;
    for (int r = 0; r < 3; r++) {
        double ws = rint(sqrt(256.0 / ratios[r]));
        double hs = rint(ws * ratios[r]);
        for (int s = 0; s < 3; s++) {
            double Wd = ws * scales[s], Hd = hs * scales[s];
            int a = r * 3 + s;
            double x1 = 7.5 - 0.5 * (Wd - 1.0);
            double y1 = 7.5 - 0.5 * (Hd - 1.0);
            double x2 = 7.5 + 0.5 * (Wd - 1.0);
            double y2 = 7.5 + 0.5 * (Hd - 1.0);
            sbx[a] = make_float4((float)x1, (float)y1, (float)x2, (float)y2);
            int ix1 = (int)llrint(x1), iy1 = (int)llrint(y1);
            int ix2 = (int)llrint(x2), iy2 = (int)llrint(y2);
            int Lx = (ix1 < 0) ? ((-ix1 + 15) / 16) : 0;
            int Ly = (iy1 < 0) ? ((-iy1 + 15) / 16) : 0;
            int nxw = 16 * W - 1 - ix2;
            int nyh = 16 * H - 1 - iy2;
            int Rx = (nxw < 0) ? -1 : min(W - 1, nxw / 16);
            int Ry = (nyh < 0) ? -1 : min(H - 1, nyh / 16);
            sb[a] = make_int4(Lx, Rx, Ly, Ry);
            int nx = Rx - Lx + 1; if (nx < 0) nx = 0;
            int ny = Ry - Ly + 1; if (ny < 0) ny = 0;
            nt += nx * ny;
        }
    }
    *Ntot = nt;
}

// ---------------- K1: setup + analytic rank + compaction + resets ------------
__global__ void k_grid(const int* pB, const int* pG, const int* pH, const int* pW) {
    __shared__ int4 sb[A_NUM];
    __shared__ float4 sbx[A_NUM];
    __shared__ int sdim[3];  // H, W, KA
    int tid = threadIdx.x;
    if (tid == 0) {
        int H = *pH, W = *pW;
        int Ntot;
        compute_anchors(H, W, sbx, sb, &Ntot);
        int KA = H * W * A_NUM;
        if (KA > KA_MAX) KA = KA_MAX;
        sdim[0] = H; sdim[1] = W; sdim[2] = KA;
        if (blockIdx.x == 0) {
            int B = *pB, G = *pG;
            if (B > B_MAX) B = B_MAX;
            if (G > G_MAX) G = G_MAX;
            Params p; p.B = B; p.G = G; p.H = H; p.W = W; p.KA = KA; p.N = Ntot;
            g_p = p;
            for (int a = 0; a < A_NUM; a++) { g_abox[a] = sbx[a]; g_bnd[a] = sb[a]; }
        }
    }
    __syncthreads();
    int ka = blockIdx.x * blockDim.x + tid;
    if (blockIdx.x == 0 && tid < B_MAX) {
        uint32_t h0 = 0u, h1 = (uint32_t)tid;
        tf2x32(0u, 42u, h0, h1);
        uint32_t f0 = 0u, f1 = 0u; tf2x32(h0, h1, f0, f1);
        uint32_t c0 = 0u, c1 = 1u; tf2x32(h0, h1, c0, c1);
        g_keyf[tid * 2 + 0] = f0; g_keyf[tid * 2 + 1] = f1;
        g_keyb[tid * 2 + 0] = c0; g_keyb[tid * 2 + 1] = c1;
    }
    if (ka < B_MAX * G_MAX) g_gtmax[ka] = 0;
    if (ka < B_MAX * 2 * 256) ((int*)g_hist)[ka] = 0;
    if (ka < B_MAX * 2) ((int*)g_candcnt)[ka] = 0;
    const int W = sdim[1], KA = sdim[2];
    const int HW = sdim[0] * W;
    if (ka >= KA) return;
    int a = ka % A_NUM;
    int cell = ka / A_NUM;
    int x = cell % W, y = cell / W;
    int rank = 0;
#pragma unroll
    for (int a2 = 0; a2 < A_NUM; a2++) {
        int4 bb = sb[a2];  // {Lx,Rx,Ly,Ry}
        int nx = bb.y - bb.x + 1; if (nx < 0) nx = 0;
        int rb = min(bb.w, y - 1) - bb.z + 1; if (rb < 0) rb = 0;
        rank += rb * nx;
        if (y >= bb.z && y <= bb.w) {
            int xb = min(bb.y, x - 1) - bb.x + 1; if (xb < 0) xb = 0;
            rank += xb;
            if (a2 < a && x >= bb.x && x <= bb.y) rank += 1;
        }
    }
    int4 mb = sb[a];
    bool inside = (x >= mb.x && x <= mb.y && y >= mb.z && y <= mb.w);
    if (inside) {
        float sx = 16.0f * (float)x, sy = 16.0f * (float)y;
        float4 o = sbx[a];
        g_anc4[rank] = make_float4(sx + o.x, sy + o.y, sx + o.z, sy + o.w);
        g_rank_t[a * HW + cell] = rank;
    } else {
        g_rank_t[a * HW + cell] = -1;
    }
}

// ---------------- K2: fused — maxov/arg/gtmax + labels + priority + hist -----
#define APT 4
__global__ void k_passA(const float* __restrict__ gt) {
    int b = blockIdx.y;
    if (b >= g_p.B) return;
    const int N = g_p.N, G = g_p.G;
    int base = blockIdx.x * (256 * APT);
    if (base >= N) return;
    __shared__ float4 sgt[G_MAX];
    __shared__ float sga[G_MAX];
    __shared__ int sgmx[G_MAX];
    __shared__ int shf[256], shb[256];
    int tid = threadIdx.x;
    shf[tid] = 0; shb[tid] = 0;
    if (tid < G_MAX) {
        float4 gb;
        if (tid < G) gb = reinterpret_cast<const float4*>(gt)[(size_t)b * G + tid];
        else gb = make_float4(2e9f, 2e9f, -2e9f, -2e9f);
        sgt[tid] = gb;
        sga[tid] = area_fn(gb.x, gb.y, gb.z, gb.w);
        sgmx[tid] = 0;
    }
    __syncthreads();
    float4 A[APT]; float area[APT]; float best[APT]; int arg[APT]; bool val[APT];
#pragma unroll
    for (int k = 0; k < APT; k++) {
        int idx = base + k * 256 + tid;
        val[k] = idx < N;
        A[k] = val[k] ? g_anc4[idx] : make_float4(3e9f, 3e9f, -3e9f, -3e9f);
        area[k] = area_fn(A[k].x, A[k].y, A[k].z, A[k].w);
        best[k] = 0.0f; arg[k] = 0;
    }
#pragma unroll
    for (int g = 0; g < G_MAX; g++) {
        if (g < G) {
            float4 gb = sgt[g]; float ag = sga[g];
            float m = 0.0f;
#pragma unroll
            for (int k = 0; k < APT; k++) {
                float iw = __fadd_rn(__fsub_rn(fminf(A[k].z, gb.z), fmaxf(A[k].x, gb.x)), 1.0f);
                float ih = __fadd_rn(__fsub_rn(fminf(A[k].w, gb.w), fmaxf(A[k].y, gb.y)), 1.0f);
                iw = fmaxf(iw, 0.0f);
                ih = fmaxf(ih, 0.0f);
                float inter = __fmul_rn(iw, ih);
                if (inter > 0.0f) {  // iou == +0 exactly when inter == 0
                    float denom = __fsub_rn(__fadd_rn(area[k], ag), inter);
                    float iou = __fdiv_rn(inter, denom);
                    if (iou > best[k]) { best[k] = iou; arg[k] = g; }
                    m = fmaxf(m, iou);
                }
            }
#pragma unroll
            for (int off = 16; off > 0; off >>= 1)
                m = fmaxf(m, __shfl_xor_sync(0xFFFFFFFFu, m, off));
            if ((tid & 31) == 0 && m > 0.0f) atomicMax(&sgmx[g], __float_as_int(m));
        }
    }
    __syncthreads();
    if (tid < G) {
        int m = sgmx[tid];
        if (m != 0) atomicMax(&g_gtmax[b * G_MAX + tid], m);
    }
    // epilogue: labels + threefry priority + shared histogram
    uint32_t kf0 = g_keyf[b * 2], kf1 = g_keyf[b * 2 + 1];
    uint32_t kb0 = g_keyb[b * 2], kb1 = g_keyb[b * 2 + 1];
#pragma unroll
    for (int k = 0; k < APT; k++) {
        if (val[k]) {
            int idx = base + k * 256 + tid;
            int lab = -1;
            if (best[k] < 0.3f) lab = 0;
            if (best[k] >= 0.7f) lab = 1;
            g_lab[(size_t)b * N_MAX + idx] = lab;
            g_arg[(size_t)b * N_MAX + idx] = (unsigned char)arg[k];
            if (lab >= 0) {
                uint32_t q0 = (lab == 1) ? kf0 : kb0;
                uint32_t q1 = (lab == 1) ? kf1 : kb1;
                uint32_t c0 = 0u, c1 = (uint32_t)idx;
                tf2x32(q0, q1, c0, c1);
                uint32_t p = (c0 ^ c1) >> 9;
                g_prio[(size_t)b * N_MAX + idx] = p;
                atomicAdd((lab == 1) ? &shf[p >> 15] : &shb[p >> 15], 1);
            }
        }
    }
    __syncthreads();
    int cf = shf[tid], cb = shb[tid];
    if (cf) atomicAdd(&g_hist[b][0][tid], cf);
    if (cb) atomicAdd(&g_hist[b][1][tid], cb);
}

// ---------------- K3: per-gt argmax-hit promotion (tight windows) ------------
__global__ void k_hit(const float* __restrict__ gt) {
    int g = blockIdx.x, b = blockIdx.y;
    if (b >= g_p.B || g >= g_p.G) return;
    float gm = __int_as_float(g_gtmax[b * G_MAX + g]);
    if (!(gm > 0.0f)) return;
    const int W = g_p.W;
    const int HW = g_p.H * W;
    const float4 gb = reinterpret_cast<const float4*>(gt)[(size_t)b * g_p.G + g];
    float areag = area_fn(gb.x, gb.y, gb.z, gb.w);
    float gw = gb.z - gb.x + 1.0f, gh = gb.w - gb.y + 1.0f;
    __shared__ int s_xlo[A_NUM], s_nx[A_NUM], s_ylo[A_NUM];
    __shared__ int s_off[A_NUM + 1];
    int tid = threadIdx.x;
    if (tid < A_NUM) {
        float4 o = g_abox[tid];
        int4 bb = g_bnd[tid];
        float aw = o.z - o.x + 1.0f, ah = o.w - o.y + 1.0f;
        float areaa = __fmul_rn(aw, ah);
        float T = (gm / (1.0f + gm)) * (areaa + areag);
        int xlo = 0, ylo = 0, nx = 0, ny = 0;
        if (T <= fminf(areaa, areag) + 4.0f) {
            float wxr = fmaxf(T / fminf(ah, gh) - 4.0f, 1.0f);
            float wyr = fmaxf(T / fminf(aw, gw) - 4.0f, 1.0f);
            xlo = max(bb.x, (int)ceilf((gb.x + wxr - 1.0f - o.z) * 0.0625f));
            int xhi = min(bb.y, (int)floorf((gb.z - wxr + 1.0f - o.x) * 0.0625f));
            ylo = max(bb.z, (int)ceilf((gb.y + wyr - 1.0f - o.w) * 0.0625f));
            int yhi = min(bb.w, (int)floorf((gb.w - wyr + 1.0f - o.y) * 0.0625f));
            nx = xhi - xlo + 1; if (nx < 0) nx = 0;
            ny = yhi - ylo + 1; if (ny < 0) ny = 0;
        }
        s_xlo[tid] = xlo; s_ylo[tid] = ylo; s_nx[tid] = nx;
        s_off[tid + 1] = nx * ny;
    }
    __syncthreads();
    if (tid == 0) {
        s_off[0] = 0;
        for (int a = 0; a < A_NUM; a++) s_off[a + 1] += s_off[a];
    }
    __syncthreads();
    int total = s_off[A_NUM];
    uint32_t kf0 = g_keyf[b * 2], kf1 = g_keyf[b * 2 + 1];
    for (int t = tid; t < total; t += blockDim.x) {
        int a = 0;
        while (t >= s_off[a + 1]) a++;
        int u = t - s_off[a];
        int nx = s_nx[a];
        int x = s_xlo[a] + u % nx;
        int y = s_ylo[a] + u / nx;
        float4 o = g_abox[a];
        float sx = 16.0f * (float)x, sy = 16.0f * (float)y;
        float a0 = sx + o.x, a1 = sy + o.y, a2 = sx + o.z, a3 = sy + o.w;
        float areaa = area_fn(a0, a1, a2, a3);
        float iou = iou_fn(a0, a1, a2, a3, areaa, gb.x, gb.y, gb.z, gb.w, areag);
        if (iou == gm) {
            int rank = g_rank_t[a * HW + y * W + x];
            if (rank >= 0) {
                int old = atomicExch(&g_lab[(size_t)b * N_MAX + rank], 1);
                if (old != 1) {  // winner applies prio overwrite + hist fixups
                    uint32_t p_old = g_prio[(size_t)b * N_MAX + rank];
                    uint32_t c0 = 0u, c1 = (uint32_t)rank;
                    tf2x32(kf0, kf1, c0, c1);
                    uint32_t p_new = (c0 ^ c1) >> 9;
                    g_prio[(size_t)b * N_MAX + rank] = p_new;
                    if (old == 0) atomicSub(&g_hist[b][1][p_old >> 15], 1);
                    atomicAdd(&g_hist[b][0][p_new >> 15], 1);
                }
            }
        }
    }
}

// ---------------- K4a: per-image threshold bin from histograms ---------------
__global__ void k_mid() {
    int b = blockIdx.x;
    if (b >= g_p.B) return;
    int tid = threadIdx.x;  // 256 threads
    __shared__ int sc[256];
    __shared__ int s_tot;
    // fg scan
    int c = g_hist[b][0][tid];
    int v = c;
#pragma unroll
    for (int off = 1; off < 256; off <<= 1) {
        sc[tid] = v; __syncthreads();
        if (tid >= off) v += sc[tid - off];
        __syncthreads();
    }
    sc[tid] = v; __syncthreads();
    int fg = sc[255];
    if (tid == 0) {
        s_tot = fg;
        g_seldat[b][0] = (fg > 128);
        g_thr[b][0] = ~0ull; g_thr[b][1] = ~0ull;
    }
    if (fg > 128 && v >= 128 && v - c < 128) {
        g_seldat[b][1] = tid;
        g_seldat[b][2] = 128 - (v - c);
    }
    __syncthreads();
    // bg scan
    c = g_hist[b][1][tid];
    v = c;
#pragma unroll
    for (int off = 1; off < 256; off <<= 1) {
        sc[tid] = v; __syncthreads();
        if (tid >= off) v += sc[tid - off];
        __syncthreads();
    }
    sc[tid] = v; __syncthreads();
    int bg = sc[255];
    int numbg = 256 - (s_tot < 128 ? s_tot : 128);
    if (tid == 0) g_seldat[b][3] = (bg > numbg);
    if (bg > numbg && v >= numbg && v - c < numbg) {
        g_seldat[b][4] = tid;
        g_seldat[b][5] = numbg - (v - c);
    }
}

// ---------------- K4b: gather candidates in threshold bins -------------------
__global__ void k_gather() {
    int b = blockIdx.y;
    if (b >= g_p.B) return;
    __shared__ int s_d[4];
    int tid = threadIdx.x;
    if (tid < 4) {
        // needf, df, needb, db
        int idx[4] = {0, 1, 3, 4};
        s_d[tid] = g_seldat[b][idx[tid]];
    }
    __syncthreads();
    int needf = s_d[0], df = s_d[1], needb = s_d[2], db = s_d[3];
    if (!needf && !needb) return;
    const int N = g_p.N;
    int stride = gridDim.x * blockDim.x;
    for (int i = blockIdx.x * blockDim.x + tid; i < N; i += stride) {
        int l = g_lab[(size_t)b * N_MAX + i];
        if (l < 0) continue;
        uint32_t p = g_prio[(size_t)b * N_MAX + i];
        int bin = p >> 15;
        if (l == 1) {
            if (needf && bin == df) {
                int pos = atomicAdd(&g_candcnt[b][0], 1);
                if (pos < SELB)
                    g_cand[b][0][pos] = ((unsigned long long)p << 16) | (unsigned)i;
            }
        } else if (needb && bin == db) {
            int pos = atomicAdd(&g_candcnt[b][1], 1);
            if (pos < SELB)
                g_cand[b][1][pos] = ((unsigned long long)p << 16) | (unsigned)i;
        }
    }
}

// ---------------- K4c: exact k-th among candidates → thresholds --------------
__global__ void k_thr() {
    int b = blockIdx.x;
    if (b >= g_p.B) return;
    int tid = threadIdx.x;  // 512
    int needf = g_seldat[b][0], lkf = g_seldat[b][2];
    int needb = g_seldat[b][3], lkb = g_seldat[b][5];
    if (needf) {
        int m = min(g_candcnt[b][0], SELB);
        if (tid < m) {
            unsigned long long key = g_cand[b][0][tid];
            int c = 0;
            for (int j = 0; j < m; j++) c += (g_cand[b][0][j] < key);
            if (c == lkf - 1) g_thr[b][0] = key;
        }
    }
    if (needb) {
        int m = min(g_candcnt[b][1], SELB);
        if (tid < m) {
            unsigned long long key = g_cand[b][1][tid];
            int c = 0;
            for (int j = 0; j < m; j++) c += (g_cand[b][1][j] < key);
            if (c == lkb - 1) g_thr[b][1] = key;
        }
    }
}

// ---------------- K5: emit (with fused subsample rewrite) --------------------
__global__ void k_emit(const float* __restrict__ gt, float* __restrict__ out) {
    int b = blockIdx.y;
    if (b >= g_p.B) return;
    const int H = g_p.H, W = g_p.W, HW = H * W, KA = g_p.KA, G = g_p.G, B = g_p.B;
    int t = blockIdx.x * blockDim.x + threadIdx.x;  // linear over (a, y, x)
    if (t >= KA) return;
    int a = t / HW;
    int rem = t - a * HW;
    int rank = g_rank_t[t];   // transposed layout: coalesced
    float lv = -1.0f;
    float r0 = 0.f, r1 = 0.f, r2 = 0.f, r3 = 0.f;
    if (rank >= 0) {
        int l = g_lab[(size_t)b * N_MAX + rank];
        if (l >= 0) {
            unsigned long long key =
                ((unsigned long long)g_prio[(size_t)b * N_MAX + rank] << 16) |
                (unsigned)rank;
            if (key > g_thr[b][l == 1 ? 0 : 1]) l = -1;
        }
        lv = (float)l;
        if (l == 1) {
            int arg = g_arg[(size_t)b * N_MAX + rank];
            float4 av = g_anc4[rank];
            const float* gp = gt + ((size_t)b * G + arg) * 4;
            float g0 = gp[0], g1 = gp[1], g2 = gp[2], g3 = gp[3];
            float aw = av.z - av.x + 1.0f, ah = av.w - av.y + 1.0f;
            float acx = av.x + 0.5f * (aw - 1.0f), acy = av.y + 0.5f * (ah - 1.0f);
            float gw = g2 - g0 + 1.0f, gh = g3 - g1 + 1.0f;
            float gcx = g0 + 0.5f * (gw - 1.0f), gcy = g1 + 0.5f * (gh - 1.0f);
            r0 = (gcx - acx) / aw;
            r1 = (gcy - acy) / ah;
            r2 = logf(gw / aw);
            r3 = logf(gh / ah);
        }
    }
    out[((size_t)b * A_NUM + a) * HW + rem] = lv;
    float* out_reg = out + (size_t)B * A_NUM * HW;
    size_t rb = ((size_t)b * A_NUM * 4 + (size_t)a * 4) * HW + rem;
    out_reg[rb] = r0;
    out_reg[rb + HW] = r1;
    out_reg[rb + 2 * (size_t)HW] = r2;
    out_reg[rb + 3 * (size_t)HW] = r3;
}

extern "C" void kernel_launch(void* const* d_in, const int* in_sizes, int n_in,
                              void* d_out, int out_size) {
    const float* gt = (const float*)d_in[0];
    const int* pB = (const int*)d_in[1];
    const int* pG = (const int*)d_in[2];
    const int* pH = (const int*)d_in[3];
    const int* pW = (const int*)d_in[4];

    k_grid<<<(KA_MAX + 255) / 256, 256>>>(pB, pG, pH, pW);
    {
        dim3 g((N_MAX + 256 * APT - 1) / (256 * APT), B_MAX);
        k_passA<<<g, 256>>>(gt);
    }
    {
        dim3 g(G_MAX, B_MAX);
        k_hit<<<g, 128>>>(gt);
    }
    k_mid<<<B_MAX, 256>>>();
    {
        dim3 g(8, B_MAX);
        k_gather<<<g, 1024>>>();
    }
    k_thr<<<B_MAX, 512>>>();
    {
        dim3 g((KA_MAX + 255) / 256, B_MAX);
        k_emit<<<g, 256>>>(gt, (float*)d_out);
    }
}

// round 10
// speedup vs baseline: 4.0960x; 1.2521x over previous
#include <cuda_runtime.h>
#include <cstdint>
#include <math_constants.h>

#define A_NUM 9
#define KA_MAX 36864   // 64*64*9
#define N_MAX  36864
#define B_MAX  32
#define G_MAX  64
#define SELB   512
#define APT    4

struct Params { int B, G, H, W, KA, N; };
__device__ Params g_p;
__device__ int    g_rank_t[KA_MAX];          // [a][cell] inside rank or -1
__device__ float4 g_anc4[N_MAX];             // inside anchor boxes
__device__ float4 g_abox[A_NUM];
__device__ int4   g_bnd[A_NUM];              // {Lx,Rx,Ly,Ry}
__device__ uint32_t g_keyf[B_MAX * 2];
__device__ uint32_t g_keyb[B_MAX * 2];
__device__ float  g_gtmaxf[B_MAX * G_MAX];   // analytic per-gt max IoU
__device__ unsigned char g_arg[B_MAX * N_MAX];
__device__ uint32_t g_lp[B_MAX * N_MAX];     // (prio<<2) | (lab+1); 0 == lab -1
__device__ int    g_hist[B_MAX][2][256];
__device__ unsigned long long g_thr[B_MAX][2];

// ---------------- Threefry-2x32 (JAX schedule) -------------------------------
__device__ __forceinline__ uint32_t rotl32(uint32_t x, uint32_t r) {
    return __funnelshift_l(x, x, r);
}
__device__ __forceinline__ void tf2x32(uint32_t k0, uint32_t k1,
                                       uint32_t& x0, uint32_t& x1) {
    uint32_t ks2 = k0 ^ k1 ^ 0x1BD11BDAu;
    x0 += k0; x1 += k1;
    const uint32_t rA[4] = {13u, 15u, 26u, 6u};
    const uint32_t rB[4] = {17u, 29u, 16u, 24u};
#pragma unroll
    for (int i = 0; i < 4; i++) { x0 += x1; x1 = rotl32(x1, rA[i]); x1 ^= x0; }
    x0 += k1; x1 += ks2 + 1u;
#pragma unroll
    for (int i = 0; i < 4; i++) { x0 += x1; x1 = rotl32(x1, rB[i]); x1 ^= x0; }
    x0 += ks2; x1 += k0 + 2u;
#pragma unroll
    for (int i = 0; i < 4; i++) { x0 += x1; x1 = rotl32(x1, rA[i]); x1 ^= x0; }
    x0 += k0; x1 += k1 + 3u;
#pragma unroll
    for (int i = 0; i < 4; i++) { x0 += x1; x1 = rotl32(x1, rB[i]); x1 ^= x0; }
    x0 += k1; x1 += ks2 + 4u;
#pragma unroll
    for (int i = 0; i < 4; i++) { x0 += x1; x1 = rotl32(x1, rA[i]); x1 ^= x0; }
    x0 += ks2; x1 += k0 + 5u;
}

// ---------------- IoU (identical op order everywhere; no FMA contraction) ----
__device__ __forceinline__ float area_fn(float x1, float y1, float x2, float y2) {
    return __fmul_rn(__fadd_rn(__fsub_rn(x2, x1), 1.0f),
                     __fadd_rn(__fsub_rn(y2, y1), 1.0f));
}

// best float iw over integer positions in [L,R] (concave in x; candidates at
// floor/ceil(+-1) of the two breakpoints; monotone rounding keeps exactness)
__device__ __forceinline__ float axis_best(float glo, float ghi,
                                           float olo, float ohi, int L, int R) {
    float t1 = __fmul_rn(__fsub_rn(glo, olo), 0.0625f);
    float t2 = __fmul_rn(__fsub_rn(ghi, ohi), 0.0625f);
    int f1 = (int)floorf(t1), f2 = (int)floorf(t2);
    int cand[6] = {f1 - 1, f1, f1 + 1, f2 - 1, f2, f2 + 1};
    float best = -1e30f;
#pragma unroll
    for (int i = 0; i < 6; i++) {
        int x = min(max(cand[i], L), R);
        float sx = __fmul_rn(16.0f, (float)x);
        float alo = __fadd_rn(sx, olo), ahi = __fadd_rn(sx, ohi);
        float iw = __fadd_rn(__fsub_rn(fminf(ahi, ghi), fmaxf(alo, glo)), 1.0f);
        best = fmaxf(best, iw);
    }
    return best;
}

__device__ __forceinline__ void compute_anchors(int H, int W,
                                                float4* sbx, int4* sb, int* Ntot) {
    const double ratios[3] = {0.5, 1.0, 2.0};
    const double scales[3] = {8.0, 16.0, 32.0};
    int nt = 0;
    for (int r = 0; r < 3; r++) {
        double ws = rint(sqrt(256.0 / ratios[r]));
        double hs = rint(ws * ratios[r]);
        for (int s = 0; s < 3; s++) {
            double Wd = ws * scales[s], Hd = hs * scales[s];
            int a = r * 3 + s;
            double x1 = 7.5 - 0.5 * (Wd - 1.0);
            double y1 = 7.5 - 0.5 * (Hd - 1.0);
            double x2 = 7.5 + 0.5 * (Wd - 1.0);
            double y2 = 7.5 + 0.5 * (Hd - 1.0);
            sbx[a] = make_float4((float)x1, (float)y1, (float)x2, (float)y2);
            int ix1 = (int)llrint(x1), iy1 = (int)llrint(y1);
            int ix2 = (int)llrint(x2), iy2 = (int)llrint(y2);
            int Lx = (ix1 < 0) ? ((-ix1 + 15) / 16) : 0;
            int Ly = (iy1 < 0) ? ((-iy1 + 15) / 16) : 0;
            int nxw = 16 * W - 1 - ix2;
            int nyh = 16 * H - 1 - iy2;
            int Rx = (nxw < 0) ? -1 : min(W - 1, nxw / 16);
            int Ry = (nyh < 0) ? -1 : min(H - 1, nyh / 16);
            sb[a] = make_int4(Lx, Rx, Ly, Ry);
            int nx = Rx - Lx + 1; if (nx < 0) nx = 0;
            int ny = Ry - Ly + 1; if (ny < 0) ny = 0;
            nt += nx * ny;
        }
    }
    *Ntot = nt;
}

// ------ K1: setup + rank + anchor compaction + analytic gt_max + zeroing -----
__global__ void k_grid(const float* __restrict__ gt,
                       const int* pB, const int* pG, const int* pH, const int* pW) {
    __shared__ int4 sb[A_NUM];
    __shared__ float4 sbx[A_NUM];
    __shared__ int sdim[5];  // H, W, KA, B, G
    int tid = threadIdx.x;
    if (tid == 0) {
        int H = *pH, W = *pW;
        int Ntot;
        compute_anchors(H, W, sbx, sb, &Ntot);
        int KA = H * W * A_NUM;
        if (KA > KA_MAX) KA = KA_MAX;
        int B = *pB, G = *pG;
        if (B > B_MAX) B = B_MAX;
        if (G > G_MAX) G = G_MAX;
        sdim[0] = H; sdim[1] = W; sdim[2] = KA; sdim[3] = B; sdim[4] = G;
        if (blockIdx.x == 0) {
            Params p; p.B = B; p.G = G; p.H = H; p.W = W; p.KA = KA; p.N = Ntot;
            g_p = p;
            for (int a = 0; a < A_NUM; a++) { g_abox[a] = sbx[a]; g_bnd[a] = sb[a]; }
        }
    }
    __syncthreads();
    int ka = blockIdx.x * blockDim.x + tid;
    if (blockIdx.x == 0 && tid < B_MAX) {
        uint32_t h0 = 0u, h1 = (uint32_t)tid;
        tf2x32(0u, 42u, h0, h1);
        uint32_t f0 = 0u, f1 = 0u; tf2x32(h0, h1, f0, f1);
        uint32_t c0 = 0u, c1 = 1u; tf2x32(h0, h1, c0, c1);
        g_keyf[tid * 2 + 0] = f0; g_keyf[tid * 2 + 1] = f1;
        g_keyb[tid * 2 + 0] = c0; g_keyb[tid * 2 + 1] = c1;
    }
    if (ka < B_MAX * 2 * 256) ((int*)g_hist)[ka] = 0;
    const int B = sdim[3], G = sdim[4];
    // analytic per-gt max IoU
    if (ka < B_MAX * G_MAX) {
        int b = ka >> 6, g = ka & 63;
        float gm = 0.0f;
        if (b < B && g < G) {
            float4 gb = reinterpret_cast<const float4*>(gt)[(size_t)b * G + g];
            float areag = area_fn(gb.x, gb.y, gb.z, gb.w);
            for (int a = 0; a < A_NUM; a++) {
                int4 bb = sb[a];
                if (bb.y < bb.x || bb.w < bb.z) continue;
                float4 o = sbx[a];
                float bw = axis_best(gb.x, gb.z, o.x, o.z, bb.x, bb.y);
                float bh = axis_best(gb.y, gb.w, o.y, o.w, bb.z, bb.w);
                float iw = fmaxf(bw, 0.0f), ih = fmaxf(bh, 0.0f);
                float inter = __fmul_rn(iw, ih);
                if (inter > 0.0f) {
                    float areaa = area_fn(o.x, o.y, o.z, o.w);
                    float denom = __fsub_rn(__fadd_rn(areaa, areag), inter);
                    gm = fmaxf(gm, __fdiv_rn(inter, denom));
                }
            }
        }
        g_gtmaxf[ka] = gm;
    }
    const int W = sdim[1], KA = sdim[2];
    const int HW = sdim[0] * W;
    if (ka >= KA) return;
    int a = ka % A_NUM;
    int cell = ka / A_NUM;
    int x = cell % W, y = cell / W;
    int rank = 0;
#pragma unroll
    for (int a2 = 0; a2 < A_NUM; a2++) {
        int4 bb = sb[a2];
        int nx = bb.y - bb.x + 1; if (nx < 0) nx = 0;
        int rb = min(bb.w, y - 1) - bb.z + 1; if (rb < 0) rb = 0;
        rank += rb * nx;
        if (y >= bb.z && y <= bb.w) {
            int xb = min(bb.y, x - 1) - bb.x + 1; if (xb < 0) xb = 0;
            rank += xb;
            if (a2 < a && x >= bb.x && x <= bb.y) rank += 1;
        }
    }
    int4 mb = sb[a];
    bool inside = (x >= mb.x && x <= mb.y && y >= mb.z && y <= mb.w);
    if (inside) {
        float sx = __fmul_rn(16.0f, (float)x), sy = __fmul_rn(16.0f, (float)y);
        float4 o = sbx[a];
        g_anc4[rank] = make_float4(__fadd_rn(sx, o.x), __fadd_rn(sy, o.y),
                                   __fadd_rn(sx, o.z), __fadd_rn(sy, o.w));
        g_rank_t[a * HW + cell] = rank;
    } else {
        g_rank_t[a * HW + cell] = -1;
    }
}

// ------ K2: fused pass: best/arg + hit + labels + priority + histogram -------
__global__ void k_passA(const float* __restrict__ gt) {
    int b = blockIdx.y;
    if (b >= g_p.B) return;
    const int N = g_p.N, G = g_p.G;
    int base = blockIdx.x * (256 * APT);
    if (base >= N) return;
    __shared__ float4 sgt[G_MAX];
    __shared__ float sga[G_MAX], sgm[G_MAX];
    __shared__ float4 cgt[G_MAX];
    __shared__ float cga[G_MAX], cgm[G_MAX];
    __shared__ unsigned char cgi[G_MAX];
    __shared__ int shf[256], shb[256];
    __shared__ int s_ymin, s_ymax, s_scnt;
    __shared__ unsigned s_bal[2];
    int tid = threadIdx.x;
    int lane = tid & 31;
    shf[tid] = 0; shb[tid] = 0;
    if (tid == 0) { s_ymin = 0x7f7fffff; s_ymax = 0; }
    if (tid < G_MAX) {
        float4 gb;
        float gm = 0.0f;
        if (tid < G) {
            gb = reinterpret_cast<const float4*>(gt)[(size_t)b * G + tid];
            gm = g_gtmaxf[b * G_MAX + tid];
        } else {
            gb = make_float4(2e9f, 2e9f, -2e9f, -2e9f);
        }
        sgt[tid] = gb;
        sga[tid] = area_fn(gb.x, gb.y, gb.z, gb.w);
        sgm[tid] = gm;
    }
    __syncthreads();
    float4 A[APT]; float area[APT]; float best[APT]; int jarg[APT]; bool hit[APT]; bool val[APT];
    float ymn = 3e9f, ymx = -3e9f;
#pragma unroll
    for (int k = 0; k < APT; k++) {
        int idx = base + k * 256 + tid;
        val[k] = idx < N;
        A[k] = val[k] ? g_anc4[idx] : make_float4(3e9f, 3e9f, -3e9f, -3e9f);
        area[k] = area_fn(A[k].x, A[k].y, A[k].z, A[k].w);
        best[k] = 0.0f; jarg[k] = -1; hit[k] = false;
        ymn = fminf(ymn, A[k].y);
        ymx = fmaxf(ymx, A[k].w);
    }
#pragma unroll
    for (int off = 16; off > 0; off >>= 1) {
        ymn = fminf(ymn, __shfl_xor_sync(0xFFFFFFFFu, ymn, off));
        ymx = fmaxf(ymx, __shfl_xor_sync(0xFFFFFFFFu, ymx, off));
    }
    if (lane == 0) {
        atomicMin(&s_ymin, __float_as_int(ymn));
        atomicMax(&s_ymax, __float_as_int(ymx));
    }
    __syncthreads();
    float wlo = __int_as_float(s_ymin) - 4.0f;
    float whi = __int_as_float(s_ymax) + 4.0f;
    // order-preserving cull+compact of gts overlapping this block's y-strip
    bool pass = false;
    unsigned bal = 0;
    if (tid < 64) {
        if (tid < G) {
            float4 gb = sgt[tid];
            pass = (gb.w >= wlo) && (gb.y <= whi);
        }
        bal = __ballot_sync(0xFFFFFFFFu, pass);
        if (lane == 0) s_bal[tid >> 5] = bal;
    }
    __syncthreads();
    if (tid < 64 && pass) {
        int w = tid >> 5;
        int off = __popc(bal & ((1u << lane) - 1u)) + (w ? __popc(s_bal[0]) : 0);
        cgt[off] = sgt[tid]; cga[off] = sga[tid]; cgm[off] = sgm[tid];
        cgi[off] = (unsigned char)tid;
    }
    if (tid == 0) s_scnt = __popc(s_bal[0]) + __popc(s_bal[1]);
    __syncthreads();
    int scnt = s_scnt;
    for (int j = 0; j < scnt; j++) {
        float4 gb = cgt[j]; float ag = cga[j]; float gm = cgm[j];
#pragma unroll
        for (int k = 0; k < APT; k++) {
            float iw = __fadd_rn(__fsub_rn(fminf(A[k].z, gb.z), fmaxf(A[k].x, gb.x)), 1.0f);
            float ih = __fadd_rn(__fsub_rn(fminf(A[k].w, gb.w), fmaxf(A[k].y, gb.y)), 1.0f);
            iw = fmaxf(iw, 0.0f);
            ih = fmaxf(ih, 0.0f);
            float inter = __fmul_rn(iw, ih);
            if (inter > 0.0f) {   // iou == +0 exactly when inter == 0
                float denom = __fsub_rn(__fadd_rn(area[k], ag), inter);
                float iou = __fdiv_rn(inter, denom);
                hit[k] |= (iou == gm);
                if (iou > best[k]) { best[k] = iou; jarg[k] = j; }
            }
        }
    }
    // epilogue: final labels + threefry priority + shared histogram
    uint32_t kf0 = g_keyf[b * 2], kf1 = g_keyf[b * 2 + 1];
    uint32_t kb0 = g_keyb[b * 2], kb1 = g_keyb[b * 2 + 1];
#pragma unroll
    for (int k = 0; k < APT; k++) {
        if (val[k]) {
            int idx = base + k * 256 + tid;
            int lab = -1;
            if (best[k] < 0.3f) lab = 0;
            if (best[k] >= 0.7f) lab = 1;
            if (hit[k]) lab = 1;
            g_arg[(size_t)b * N_MAX + idx] =
                (jarg[k] < 0) ? (unsigned char)0 : cgi[jarg[k]];
            uint32_t word = 0u;
            if (lab >= 0) {
                uint32_t q0 = (lab == 1) ? kf0 : kb0;
                uint32_t q1 = (lab == 1) ? kf1 : kb1;
                uint32_t c0 = 0u, c1 = (uint32_t)idx;
                tf2x32(q0, q1, c0, c1);
                uint32_t p = (c0 ^ c1) >> 9;
                word = (p << 2) | (uint32_t)(lab + 1);
                atomicAdd((lab == 1) ? &shf[p >> 15] : &shb[p >> 15], 1);
            }
            g_lp[(size_t)b * N_MAX + idx] = word;
        }
    }
    __syncthreads();
    int cf = shf[tid], cb = shb[tid];
    if (cf) atomicAdd(&g_hist[b][0][tid], cf);
    if (cb) atomicAdd(&g_hist[b][1][tid], cb);
}

// ------ K3: fused subsample: scans -> gather -> exact k-th -> thresholds -----
__global__ void k_select() {
    int b = blockIdx.x;
    if (b >= g_p.B) return;
    int tid = threadIdx.x, lane = tid & 31, w = tid >> 5;
    __shared__ int s_ws[8], s_ws2[8];
    __shared__ int s_inf[8];  // 1 df, 2 lkf, 3 needf, 5 db, 6 lkb, 7 needb
    __shared__ unsigned long long sf[SELB], sbb[SELB];
    __shared__ int s_cf, s_cb;
    if (tid == 0) { s_cf = 0; s_cb = 0; s_inf[3] = 0; s_inf[7] = 0; }
    int cf = 0, cumf = 0, cb2 = 0, cumb = 0;
    if (tid < 256) {
        cf = g_hist[b][0][tid];
        cb2 = g_hist[b][1][tid];
        int v = cf;
#pragma unroll
        for (int o = 1; o < 32; o <<= 1) {
            int u = __shfl_up_sync(0xFFFFFFFFu, v, o);
            if (lane >= o) v += u;
        }
        if (lane == 31) s_ws[w] = v;
        cumf = v;
        v = cb2;
#pragma unroll
        for (int o = 1; o < 32; o <<= 1) {
            int u = __shfl_up_sync(0xFFFFFFFFu, v, o);
            if (lane >= o) v += u;
        }
        if (lane == 31) s_ws2[w] = v;
        cumb = v;
    }
    __syncthreads();
    if (tid == 0) {
        int acc = 0;
        for (int i = 0; i < 8; i++) { acc += s_ws[i]; s_ws[i] = acc; }
        acc = 0;
        for (int i = 0; i < 8; i++) { acc += s_ws2[i]; s_ws2[i] = acc; }
    }
    __syncthreads();
    int fgtot = s_ws[7];
    int bgtot = s_ws2[7];
    int numbg = 256 - min(fgtot, 128);
    if (tid < 256) {
        if (w > 0) { cumf += s_ws[w - 1]; cumb += s_ws2[w - 1]; }
        if (fgtot > 128 && cumf >= 128 && cumf - cf < 128) {
            s_inf[1] = tid; s_inf[2] = 128 - (cumf - cf); s_inf[3] = 1;
        }
        if (bgtot > numbg && cumb >= numbg && cumb - cb2 < numbg) {
            s_inf[5] = tid; s_inf[6] = numbg - (cumb - cb2); s_inf[7] = 1;
        }
    }
    __syncthreads();
    int needf = s_inf[3], df = s_inf[1], lkf = s_inf[2];
    int needb = s_inf[7], db = s_inf[5], lkb = s_inf[6];
    if (tid == 0) {
        if (!needf) g_thr[b][0] = ~0ull;
        if (!needb) g_thr[b][1] = ~0ull;
    }
    if (needf || needb) {
        const int N = g_p.N;
        const uint32_t* lp = g_lp + (size_t)b * N_MAX;
        for (int i = tid; i < N; i += 1024) {
            uint32_t wd = lp[i];
            if (!wd) continue;
            int bin = (wd >> 17) & 0xFF;
            if ((wd & 3u) == 2u) {
                if (needf && bin == df) {
                    int pos = atomicAdd(&s_cf, 1);
                    if (pos < SELB)
                        sf[pos] = ((unsigned long long)(wd >> 2) << 16) | (unsigned)i;
                }
            } else {
                if (needb && bin == db) {
                    int pos = atomicAdd(&s_cb, 1);
                    if (pos < SELB)
                        sbb[pos] = ((unsigned long long)(wd >> 2) << 16) | (unsigned)i;
                }
            }
        }
        __syncthreads();
        int mf = min(s_cf, SELB), mb = min(s_cb, SELB);
        if (needf && tid < mf) {
            unsigned long long key = sf[tid];
            int c = 0;
            for (int j = 0; j < mf; j++) c += (sf[j] < key);
            if (c == lkf - 1) g_thr[b][0] = key;
        }
        if (needb && tid < mb) {
            unsigned long long key = sbb[tid];
            int c = 0;
            for (int j = 0; j < mb; j++) c += (sbb[j] < key);
            if (c == lkb - 1) g_thr[b][1] = key;
        }
    }
}

// ------ K4: emit labels [B,9,H,W] + reg [B,36,H,W] (fused rewrite) -----------
__global__ void k_emit(const float* __restrict__ gt, float* __restrict__ out) {
    int b = blockIdx.y;
    if (b >= g_p.B) return;
    const int H = g_p.H, W = g_p.W, HW = H * W, KA = g_p.KA, G = g_p.G, B = g_p.B;
    int t = blockIdx.x * blockDim.x + threadIdx.x;
    if (t >= KA) return;
    int a = t / HW;
    int rem = t - a * HW;
    int rank = g_rank_t[t];
    float lv = -1.0f;
    float r0 = 0.f, r1 = 0.f, r2 = 0.f, r3 = 0.f;
    if (rank >= 0) {
        uint32_t wd = g_lp[(size_t)b * N_MAX + rank];
        int l = (int)(wd & 3u) - 1;
        if (l >= 0) {
            unsigned long long key =
                ((unsigned long long)(wd >> 2) << 16) | (unsigned)rank;
            if (key > g_thr[b][l == 1 ? 0 : 1]) l = -1;
        }
        lv = (float)l;
        if (l == 1) {
            int arg = g_arg[(size_t)b * N_MAX + rank];
            float4 av = g_anc4[rank];
            const float* gp = gt + ((size_t)b * G + arg) * 4;
            float g0 = gp[0], g1 = gp[1], g2 = gp[2], g3 = gp[3];
            float aw = av.z - av.x + 1.0f, ah = av.w - av.y + 1.0f;
            float acx = av.x + 0.5f * (aw - 1.0f), acy = av.y + 0.5f * (ah - 1.0f);
            float gw = g2 - g0 + 1.0f, gh = g3 - g1 + 1.0f;
            float gcx = g0 + 0.5f * (gw - 1.0f), gcy = g1 + 0.5f * (gh - 1.0f);
            r0 = (gcx - acx) / aw;
            r1 = (gcy - acy) / ah;
            r2 = logf(gw / aw);
            r3 = logf(gh / ah);
        }
    }
    out[((size_t)b * A_NUM + a) * HW + rem] = lv;
    float* out_reg = out + (size_t)B * A_NUM * HW;
    size_t rb = ((size_t)b * A_NUM * 4 + (size_t)a * 4) * HW + rem;
    out_reg[rb] = r0;
    out_reg[rb + HW] = r1;
    out_reg[rb + 2 * (size_t)HW] = r2;
    out_reg[rb + 3 * (size_t)HW] = r3;
}

extern "C" void kernel_launch(void* const* d_in, const int* in_sizes, int n_in,
                              void* d_out, int out_size) {
    const float* gt = (const float*)d_in[0];
    const int* pB = (const int*)d_in[1];
    const int* pG = (const int*)d_in[2];
    const int* pH = (const int*)d_in[3];
    const int* pW = (const int*)d_in[4];

    k_grid<<<(KA_MAX + 255) / 256, 256>>>(gt, pB, pG, pH, pW);
    {
        dim3 g((N_MAX + 256 * APT - 1) / (256 * APT), B_MAX);
        k_passA<<<g, 256>>>(gt);
    }
    k_select<<<B_MAX, 1024>>>();
    {
        dim3 g((KA_MAX + 255) / 256, B_MAX);
        k_emit<<<g, 256>>>(gt, (float*)d_out);
    }
}